// round 13
// baseline (speedup 1.0000x reference)
#include <cuda_runtime.h>
#include <cuda_bf16.h>
#include <cstdint>

#define N_TOK 32768
#define DIM   256
#define NCODE 1024
#define TAU   3.0f
#define TAU2  0.75f
#define CAP   48

// d_out layout (float32): z_q_st, loss, indices, new_cluster_size,
// new_embedding_avg, new_embedding
#define OFF_ZQ   0
#define OFF_LOSS (N_TOK * DIM)
#define OFF_IDX  (OFF_LOSS + 1)
#define OFF_CS   (OFF_IDX + N_TOK)
#define OFF_AVG  (OFF_CS + NCODE)
#define OFF_EMB  (OFF_AVG + NCODE * DIM)

#define TILE_B   10240                   // 128 rows x 80 B (64 B data + pad)

__device__ __align__(16) float g_enorm[NCODE];
__device__ float g_counts[NCODE];
__device__ __align__(16) float g_esum[NCODE * DIM];
__device__ float g_loss;
__device__ float g_nsum;
// tile-contiguous bf16 images: gAt[block][kc][row*80 + c*2], gBt[n][kc][...]
__device__ __align__(16) uint8_t gAt[(N_TOK / 128) * 8 * TILE_B];   // 21 MB
__device__ __align__(16) uint8_t gBt[(NCODE / 128) * 8 * TILE_B];   // 655 KB
__device__ int g_cnt[N_TOK];
__device__ unsigned g_minu[N_TOK];
__device__ unsigned long long g_cand64[N_TOK * CAP];   // (mapped dist, code)

// ---------------------------------------------------------------------------
__device__ __forceinline__ uint32_t smem_u32(const void* p) {
    uint32_t a;
    asm("{ .reg .u64 t; cvta.to.shared.u64 t, %1; cvt.u32.u64 %0, t; }"
        : "=r"(a) : "l"(p));
    return a;
}
#define MBAR_INIT(a, c) asm volatile("mbarrier.init.shared.b64 [%0], %1;" \
    :: "r"(a), "r"(c) : "memory")
#define MBAR_EXPECT_TX(a, b) asm volatile(                                    \
    "mbarrier.arrive.expect_tx.shared.b64 _, [%0], %1;"                       \
    :: "r"(a), "r"(b) : "memory")
#define MBAR_WAIT(a, ph) do {                                               \
    uint32_t _m = (a), _p = (ph), _d;                                       \
    asm volatile("{\n\t.reg .pred p;\n\t"                                   \
        "mbarrier.try_wait.parity.acquire.cta.shared::cta.b64 p, [%1], %2;\n\t" \
        "selp.b32 %0, 1, 0, p;\n\t}" : "=r"(_d) : "r"(_m), "r"(_p) : "memory"); \
    if (!_d) {                                                              \
        asm volatile("{\n\t.reg .pred P1;\n\tWL%=:\n\t"                     \
            "mbarrier.try_wait.parity.acquire.cta.shared::cta.b64 P1, [%0], %1, 0x989680;\n\t" \
            "@P1 bra.uni WD%=;\n\tbra.uni WL%=;\n\tWD%=:\n\t}"              \
            :: "r"(_m), "r"(_p) : "memory");                                \
    } } while (0)
#define FENCE_ASYNC() asm volatile("fence.proxy.async.shared::cta;" ::: "memory")

__device__ __forceinline__ void bulk_g2s(uint32_t dst, const void* src,
                                         uint32_t bytes, uint32_t mbar) {
    asm volatile(
        "cp.async.bulk.shared::cta.global.mbarrier::complete_tx::bytes "
        "[%0], [%1], %2, [%3];"
        :: "r"(dst), "l"(__cvta_generic_to_global(src)), "r"(bytes), "r"(mbar)
        : "memory");
}
__device__ __forceinline__ void red_add_v4(float* gptr, float4 v) {
    asm volatile("red.global.add.v4.f32 [%0], {%1, %2, %3, %4};"
                 :: "l"(__cvta_generic_to_global(gptr)),
                    "f"(v.x), "f"(v.y), "f"(v.z), "f"(v.w) : "memory");
}

#define LDSM4(r0, r1, r2, r3, addr) asm volatile(                              \
    "ldmatrix.sync.aligned.m8n8.x4.shared.b16 {%0,%1,%2,%3}, [%4];"            \
    : "=r"(r0), "=r"(r1), "=r"(r2), "=r"(r3) : "r"(addr))

#define MMA(c, a0, a1, a2, a3, b0, b1) asm volatile(                           \
    "mma.sync.aligned.m16n8k16.row.col.f32.bf16.bf16.f32 "                     \
    "{%0,%1,%2,%3},{%4,%5,%6,%7},{%8,%9},{%0,%1,%2,%3};"                       \
    : "+f"((c)[0]), "+f"((c)[1]), "+f"((c)[2]), "+f"((c)[3])                   \
    : "r"(a0), "r"(a1), "r"(a2), "r"(a3), "r"(b0), "r"(b1))

__device__ __forceinline__ unsigned mapf(float d) {
    unsigned u = __float_as_uint(d);
    return (u & 0x80000000u) ? ~u : (u | 0x80000000u);
}
__device__ __forceinline__ float unmapf(unsigned x) {
    return (x & 0x80000000u) ? __uint_as_float(x & 0x7fffffffu)
                             : __uint_as_float(~x);
}

// ---------------------------------------------------------------------------
__global__ void enorm_kernel(const float* __restrict__ emb) {
    int w = (blockIdx.x * blockDim.x + threadIdx.x) >> 5;
    int lane = threadIdx.x & 31;
    if (w >= NCODE) return;
    const float4* p = (const float4*)(emb + (size_t)w * DIM);
    float s = 0.0f;
#pragma unroll
    for (int c = 0; c < 2; c++) {
        float4 v = p[lane + 32 * c];
        s += v.x * v.x + v.y * v.y + v.z * v.z + v.w * v.w;
    }
#pragma unroll
    for (int o = 16; o >= 1; o >>= 1) s += __shfl_xor_sync(0xffffffffu, s, o);
    if (lane == 0) g_enorm[w] = s;
}

// prep: fp32 -> bf16 into tile-contiguous layout; also zeroes scratch.
#define AC (N_TOK * DIM / 8)             // 1,048,576
#define BC (NCODE * DIM / 8)             // 32,768
#define ZC (NCODE * DIM / 4)             // 65,536
__global__ void prep_kernel(const float* __restrict__ z, const float* __restrict__ emb) {
    int p = blockIdx.x * blockDim.x + threadIdx.x;
    if (p < AC) {
        int t = p >> 9, w = p & 511;             // tile, chunk-within
        int row = w >> 2, c4 = w & 3;
        int b = t >> 3, kc = t & 7;
        const float* src = z + (size_t)(b * 128 + row) * DIM + kc * 32 + c4 * 8;
        float4 v0 = *(const float4*)src;
        float4 v1 = *(const float4*)(src + 4);
        __nv_bfloat162 o0 = __halves2bfloat162(__float2bfloat16_rn(v0.x), __float2bfloat16_rn(v0.y));
        __nv_bfloat162 o1 = __halves2bfloat162(__float2bfloat16_rn(v0.z), __float2bfloat16_rn(v0.w));
        __nv_bfloat162 o2 = __halves2bfloat162(__float2bfloat16_rn(v1.x), __float2bfloat16_rn(v1.y));
        __nv_bfloat162 o3 = __halves2bfloat162(__float2bfloat16_rn(v1.z), __float2bfloat16_rn(v1.w));
        uint4 pack = {*(uint32_t*)&o0, *(uint32_t*)&o1, *(uint32_t*)&o2, *(uint32_t*)&o3};
        *(uint4*)(gAt + (size_t)t * TILE_B + row * 80 + c4 * 16) = pack;
    } else if (p < AC + BC) {
        int q = p - AC;
        int t = q >> 9, w = q & 511;
        int row = w >> 2, c4 = w & 3;
        int n = t >> 3, kc = t & 7;
        const float* src = emb + (size_t)(n * 128 + row) * DIM + kc * 32 + c4 * 8;
        float4 v0 = *(const float4*)src;
        float4 v1 = *(const float4*)(src + 4);
        __nv_bfloat162 o0 = __halves2bfloat162(__float2bfloat16_rn(v0.x), __float2bfloat16_rn(v0.y));
        __nv_bfloat162 o1 = __halves2bfloat162(__float2bfloat16_rn(v0.z), __float2bfloat16_rn(v0.w));
        __nv_bfloat162 o2 = __halves2bfloat162(__float2bfloat16_rn(v1.x), __float2bfloat16_rn(v1.y));
        __nv_bfloat162 o3 = __halves2bfloat162(__float2bfloat16_rn(v1.z), __float2bfloat16_rn(v1.w));
        uint4 pack = {*(uint32_t*)&o0, *(uint32_t*)&o1, *(uint32_t*)&o2, *(uint32_t*)&o3};
        *(uint4*)(gBt + (size_t)t * TILE_B + row * 80 + c4 * 16) = pack;
    } else {
        int zi = p - AC - BC;
        if (zi >= ZC) return;
        ((float4*)g_esum)[zi] = make_float4(0.f, 0.f, 0.f, 0.f);
        if (zi < NCODE / 4) ((float4*)g_counts)[zi] = make_float4(0.f, 0.f, 0.f, 0.f);
        if (zi == 0) g_loss = 0.0f;
    }
}

// ---------------------------------------------------------------------------
// Main: bulk-copy-fed bf16 HMMA approx GEMM + windowed candidate collection.
// ---------------------------------------------------------------------------
#define STAGE_SZ 20480                   // A 10240 + B 10240
#define SM_EN    81920                   // 4 KB
#define SM_MINU  86016                   // 128 x u32
#define SM_CNT   86528                   // 128 x int
#define SM_MBAR  87040                   // 4 x 8 B
#define SM_TOTAL 87104

__global__ __launch_bounds__(256, 2)
void vq_main_kernel(int blkOff) {
    extern __shared__ char smem[];
    const uint32_t sb = smem_u32(smem);
    const int tid  = threadIdx.x;
    const int lane = tid & 31;
    const int wid  = tid >> 5;
    const int wm   = wid >> 2;           // 0..1  (M half)
    const int wn   = wid & 3;            // 0..3  (N quarter, 32 cols)
    const int blk  = blockIdx.x + blkOff;
    const int rowBase = blk * 128;

    float*    sEnorm = (float*)(smem + SM_EN);
    unsigned* sMinU  = (unsigned*)(smem + SM_MINU);
    int*      sCnt   = (int*)(smem + SM_CNT);

#pragma unroll
    for (int i = 0; i < 4; i++) sEnorm[tid + i * 256] = g_enorm[tid + i * 256];
    if (tid < 128) { sMinU[tid] = 0xffffffffu; sCnt[tid] = 0; }
    if (tid == 0) {
#pragma unroll
        for (int s = 0; s < 4; s++) MBAR_INIT(sb + SM_MBAR + s * 8, 1);
    }
    __syncthreads();
    FENCE_ASYNC();

    // producer: j = n*8 + kc
#define ISSUE(j) do {                                                          \
    int _s = (j) & 3;                                                          \
    uint32_t _st = sb + _s * STAGE_SZ;                                         \
    uint32_t _mb = sb + SM_MBAR + _s * 8;                                      \
    MBAR_EXPECT_TX(_mb, STAGE_SZ);                                             \
    bulk_g2s(_st, gAt + (size_t)(blk * 8 + ((j) & 7)) * TILE_B,                \
             TILE_B, _mb);                                                     \
    bulk_g2s(_st + TILE_B, gBt + (size_t)(j) * TILE_B, TILE_B, _mb);           \
} while (0)

    if (tid == 0) { ISSUE(0); ISSUE(1); ISSUE(2); }

    // ldmatrix per-lane address offsets (bytes), row stride 80B
    const uint32_t aOff = (uint32_t)((wm * 64 + (lane & 15)) * 80 + (lane >> 4) * 16);
    const uint32_t bOff = (uint32_t)((wn * 32 + (lane & 7) + ((lane >> 4) << 3)) * 80
                                     + ((lane >> 3) & 1) * 16);

    float acc[4][4][4];
#pragma unroll
    for (int m = 0; m < 4; m++)
#pragma unroll
        for (int nf = 0; nf < 4; nf++)
#pragma unroll
            for (int v = 0; v < 4; v++) acc[m][nf][v] = 0.0f;

    // smem counter, direct global store of packed (dist, code)
#define EMIT(dd, cc, rloc) do {                                                \
    int _p = atomicAdd(&sCnt[rloc], 1);                                        \
    if (_p < CAP)                                                              \
        g_cand64[(size_t)(rowBase + (rloc)) * CAP + _p] =                      \
            ((unsigned long long)mapf(dd) << 32) | (unsigned)(cc);             \
} while (0)

    for (int it = 0; it < 64; it++) {
        MBAR_WAIT(sb + SM_MBAR + (it & 3) * 8, (it >> 2) & 1);
        // stage (it+3)&3 == (it-1)&3 was consumed before the barrier at the
        // end of iteration it-1, so re-arm it now for max overlap.
        if (tid == 0 && it + 3 < 64) ISSUE(it + 3);

        const uint32_t stBase = sb + (it & 3) * STAGE_SZ;
        const uint32_t aB = stBase + aOff;
        const uint32_t bB = stBase + TILE_B + bOff;

#pragma unroll
        for (int s = 0; s < 2; s++) {                    // two k16 steps
            uint32_t b[4][2];
#pragma unroll
            for (int q = 0; q < 2; q++) {
                uint32_t r0, r1, r2, r3;
                LDSM4(r0, r1, r2, r3, bB + q * 1280 + s * 32);
                b[2 * q][0] = r0; b[2 * q][1] = r1;
                b[2 * q + 1][0] = r2; b[2 * q + 1][1] = r3;
            }
#pragma unroll
            for (int m = 0; m < 4; m++) {
                uint32_t a0, a1, a2, a3;
                LDSM4(a0, a1, a2, a3, aB + m * 1280 + s * 32);
#pragma unroll
                for (int nf = 0; nf < 4; nf++)
                    MMA(acc[m][nf], a0, a1, a2, a3, b[nf][0], b[nf][1]);
            }
        }

        if ((it & 7) == 7) {                             // end of n-tile
            const int n = it >> 3;
            const int colB = n * 128 + wn * 32 + 2 * (lane & 3);
            // pass 1: settle per-row approx min
#pragma unroll
            for (int m = 0; m < 4; m++) {
                int r0 = wm * 64 + m * 16 + (lane >> 2);
                float bd0 = 3.4e38f, bd1 = 3.4e38f;
#pragma unroll
                for (int nf = 0; nf < 4; nf++) {
                    float2 en = *(const float2*)&sEnorm[colB + nf * 8];
                    bd0 = fminf(bd0, fminf(en.x - 2.0f * acc[m][nf][0],
                                           en.y - 2.0f * acc[m][nf][1]));
                    bd1 = fminf(bd1, fminf(en.x - 2.0f * acc[m][nf][2],
                                           en.y - 2.0f * acc[m][nf][3]));
                }
#pragma unroll
                for (int off = 1; off <= 2; off <<= 1) {
                    bd0 = fminf(bd0, __shfl_xor_sync(0xffffffffu, bd0, off));
                    bd1 = fminf(bd1, __shfl_xor_sync(0xffffffffu, bd1, off));
                }
                if ((lane & 3) == 0) {
                    atomicMin(&sMinU[r0], mapf(bd0));
                    atomicMin(&sMinU[r0 + 8], mapf(bd1));
                }
            }
            __syncthreads();
            // pass 2: emit candidates within TAU of settled min
#pragma unroll
            for (int m = 0; m < 4; m++) {
                int r0 = wm * 64 + m * 16 + (lane >> 2);
                float thr0 = unmapf(sMinU[r0]) + TAU;
                float thr1 = unmapf(sMinU[r0 + 8]) + TAU;
#pragma unroll
                for (int nf = 0; nf < 4; nf++) {
                    float2 en = *(const float2*)&sEnorm[colB + nf * 8];
                    float d0 = en.x - 2.0f * acc[m][nf][0];
                    float d1 = en.y - 2.0f * acc[m][nf][1];
                    float d2 = en.x - 2.0f * acc[m][nf][2];
                    float d3 = en.y - 2.0f * acc[m][nf][3];
                    int c0 = colB + nf * 8;
                    if (d0 < thr0) EMIT(d0, c0,     r0);
                    if (d1 < thr0) EMIT(d1, c0 + 1, r0);
                    if (d2 < thr1) EMIT(d2, c0,     r0 + 8);
                    if (d3 < thr1) EMIT(d3, c0 + 1, r0 + 8);
                    acc[m][nf][0] = 0.0f; acc[m][nf][1] = 0.0f;
                    acc[m][nf][2] = 0.0f; acc[m][nf][3] = 0.0f;
                }
            }
        }
        __syncthreads();                                 // stage consumed
    }

    // dump counts (clamped) + final per-row approx min
    if (tid < 128) {
        int c = sCnt[tid];
        g_cnt[rowBase + tid]  = c > CAP ? CAP : c;
        g_minu[rowBase + tid] = sMinU[tid];
    }
}

// ---------------------------------------------------------------------------
// Refine + output kernel: 256 threads per CTA, 16 rows per CTA.
// ---------------------------------------------------------------------------
__global__ __launch_bounds__(256, 8)
void outref_kernel(const float* __restrict__ z, const float* __restrict__ emb,
                   float* __restrict__ out, int rowOff) {
    __shared__ int   sBestC[16];
    __shared__ float sRed[8];
    const int tid  = threadIdx.x;
    const int lane = tid & 31;
    const int wid  = tid >> 5;
    const int rowBase = rowOff + blockIdx.x * 16;

#pragma unroll
    for (int rr = 0; rr < 2; rr++) {
        int r = rowBase + wid * 2 + rr;
        int cnt = g_cnt[r];
        unsigned mthr = mapf(unmapf(g_minu[r]) + TAU2);
        const float* zr = z + (size_t)r * DIM;
        float zv[8];
#pragma unroll
        for (int j = 0; j < 8; j++) zv[j] = zr[lane + 32 * j];
        float bestd = 3.4e38f; int bestc = 0x7fffffff;
        for (int base = 0; base < cnt; base += 32) {     // almost always 1 pass
            int ci = base + lane;
            unsigned long long pk = ~0ull;
            if (ci < cnt) pk = g_cand64[(size_t)r * CAP + ci];  // coalesced
            bool pass = (ci < cnt) && ((unsigned)(pk >> 32) <= mthr);
            unsigned msk = __ballot_sync(0xffffffffu, pass);
            while (msk) {                                // survivors: ~1-2
                int src = __ffs(msk) - 1; msk &= msk - 1;
                unsigned long long cpk = __shfl_sync(0xffffffffu, pk, src);
                int c = (int)(unsigned)(cpk & 0xffffffffull);
                const float* er = emb + (size_t)c * DIM;
                float dot = 0.0f;
#pragma unroll
                for (int j = 0; j < 8; j++) dot += zv[j] * er[lane + 32 * j];
#pragma unroll
                for (int o = 16; o >= 1; o >>= 1)
                    dot += __shfl_xor_sync(0xffffffffu, dot, o);
                float dd = g_enorm[c] - 2.0f * dot;
                if (dd < bestd || (dd == bestd && c < bestc)) { bestd = dd; bestc = c; }
            }
        }
        if (lane == 0) {
            sBestC[wid * 2 + rr] = bestc;
            out[OFF_IDX + r] = (float)bestc;
            atomicAdd(&g_counts[bestc], 1.0f);
        }
    }
    __syncthreads();

    // phase B: 4 row-groups x 64 column-threads, float4 everywhere
    float lossAcc = 0.0f;
    const int c4 = (tid & 63) * 4;
    const int rg = tid >> 6;
#pragma unroll
    for (int k = 0; k < 4; k++) {
        int rr   = rg * 4 + k;
        int code = sBestC[rr];
        int row  = rowBase + rr;
        float4 e  = *(const float4*)(emb + (size_t)code * DIM + c4);
        float4 zv = *(const float4*)(z + (size_t)row * DIM + c4);
        float4 df = make_float4(e.x - zv.x, e.y - zv.y, e.z - zv.z, e.w - zv.w);
        float4 q  = make_float4(zv.x + df.x, zv.y + df.y, zv.z + df.z, zv.w + df.w);
        *(float4*)(out + OFF_ZQ + (size_t)row * DIM + c4) = q;
        lossAcc += df.x * df.x + df.y * df.y + df.z * df.z + df.w * df.w;
        red_add_v4(&g_esum[code * DIM + c4], zv);
    }
#pragma unroll
    for (int o = 16; o >= 1; o >>= 1) lossAcc += __shfl_xor_sync(0xffffffffu, lossAcc, o);
    if (lane == 0) sRed[wid] = lossAcc;
    __syncthreads();
    if (tid < 8) {
        float v = sRed[tid];
#pragma unroll
        for (int o = 4; o >= 1; o >>= 1) v += __shfl_xor_sync(0xffu, v, o, 8);
        if (tid == 0) atomicAdd(&g_loss, v);
    }
}

// ---------------------------------------------------------------------------
__global__ void fin1_kernel(const float* __restrict__ cs, float* __restrict__ out) {
    int k = threadIdx.x;
    float ncs = cs[k] * 0.99f + 0.01f * g_counts[k];
    out[OFF_CS + k] = ncs;
    __shared__ float red[32];
    float v = ncs;
#pragma unroll
    for (int o = 16; o >= 1; o >>= 1) v += __shfl_xor_sync(0xffffffffu, v, o);
    if ((k & 31) == 0) red[k >> 5] = v;
    __syncthreads();
    if (k < 32) {
        float t = red[k];
#pragma unroll
        for (int o = 16; o >= 1; o >>= 1) t += __shfl_xor_sync(0xffffffffu, t, o);
        if (k == 0) {
            g_nsum = t;
            out[OFF_LOSS] = 0.25f * g_loss / (float)(N_TOK * DIM);
        }
    }
}

__global__ void fin2_kernel(const float* __restrict__ avg, float* __restrict__ out) {
    int i = blockIdx.x * blockDim.x + threadIdx.x;
    float navg = avg[i] * 0.99f + 0.01f * g_esum[i];
    out[OFF_AVG + i] = navg;
    int k = i >> 8;
    float ncs = out[OFF_CS + k];
    float csn = (ncs + 1e-6f) / (g_nsum + (float)NCODE * 1e-6f);
    out[OFF_EMB + i] = navg / csn;
}

// ---------------------------------------------------------------------------
// Fork-join pipeline: mainA -> { outrefA (s2) || mainB (s0) } -> outrefB.
// Streams/events are host objects (no device memory); created per call and
// leaked (kernel_launch is invoked only a handful of times).
// ---------------------------------------------------------------------------
extern "C" void kernel_launch(void* const* d_in, const int* in_sizes, int n_in,
                              void* d_out, int out_size) {
    const float* z   = (const float*)d_in[0];
    const float* emb = (const float*)d_in[1];
    const float* cs  = (const float*)d_in[2];
    const float* avg = (const float*)d_in[3];
    float* out = (float*)d_out;

    cudaFuncSetAttribute(vq_main_kernel,
                         cudaFuncAttributeMaxDynamicSharedMemorySize, SM_TOTAL);

    cudaStream_t s2;
    cudaStreamCreateWithFlags(&s2, cudaStreamNonBlocking);
    cudaEvent_t e1, e2;
    cudaEventCreateWithFlags(&e1, cudaEventDisableTiming);
    cudaEventCreateWithFlags(&e2, cudaEventDisableTiming);

    enorm_kernel<<<(NCODE * 32) / 256, 256>>>(emb);
    prep_kernel<<<(AC + BC + ZC + 255) / 256, 256>>>(z, emb);
    // first half of the GEMM (rows 0 .. 16383)
    vq_main_kernel<<<128, 256, SM_TOTAL>>>(0);
    cudaEventRecord(e1, 0);
    cudaStreamWaitEvent(s2, e1, 0);
    // outref for first half overlaps second-half GEMM
    outref_kernel<<<1024, 256, 0, s2>>>(z, emb, out, 0);
    vq_main_kernel<<<128, 256, SM_TOTAL>>>(128);
    cudaEventRecord(e2, s2);
    cudaStreamWaitEvent(0, e2, 0);
    outref_kernel<<<1024, 256>>>(z, emb, out, N_TOK / 2);
    fin1_kernel<<<1, 1024>>>(cs, out);
    fin2_kernel<<<(NCODE * DIM) / 256, 256>>>(avg, out);
}

// round 14
// speedup vs baseline: 1.4211x; 1.4211x over previous
#include <cuda_runtime.h>
#include <cuda_bf16.h>
#include <cstdint>

#define N_TOK 32768
#define DIM   256
#define NCODE 1024
#define TAU   3.0f
#define TAU2  0.75f
#define CAP   48

// d_out layout (float32): z_q_st, loss, indices, new_cluster_size,
// new_embedding_avg, new_embedding
#define OFF_ZQ   0
#define OFF_LOSS (N_TOK * DIM)
#define OFF_IDX  (OFF_LOSS + 1)
#define OFF_CS   (OFF_IDX + N_TOK)
#define OFF_AVG  (OFF_CS + NCODE)
#define OFF_EMB  (OFF_AVG + NCODE * DIM)

#define TILE_B   10240                   // 128 rows x 80 B (64 B data + pad)

__device__ __align__(16) float g_enorm[NCODE];
__device__ float g_counts[NCODE];
__device__ __align__(16) float g_esum[NCODE * DIM];
__device__ float g_loss;
__device__ float g_nsum;
// tile-contiguous bf16 images: gAt[block][kc][row*80 + c*2], gBt[n][kc][...]
__device__ __align__(16) uint8_t gAt[(N_TOK / 128) * 8 * TILE_B];   // 21 MB
__device__ __align__(16) uint8_t gBt[(NCODE / 128) * 8 * TILE_B];   // 655 KB
__device__ int g_cnt[N_TOK];
__device__ unsigned g_minu[N_TOK];
__device__ unsigned long long g_cand64[N_TOK * CAP];   // (mapped dist, code)

// ---------------------------------------------------------------------------
__device__ __forceinline__ uint32_t smem_u32(const void* p) {
    uint32_t a;
    asm("{ .reg .u64 t; cvta.to.shared.u64 t, %1; cvt.u32.u64 %0, t; }"
        : "=r"(a) : "l"(p));
    return a;
}
#define MBAR_INIT(a, c) asm volatile("mbarrier.init.shared.b64 [%0], %1;" \
    :: "r"(a), "r"(c) : "memory")
#define MBAR_EXPECT_TX(a, b) asm volatile(                                    \
    "mbarrier.arrive.expect_tx.shared.b64 _, [%0], %1;"                       \
    :: "r"(a), "r"(b) : "memory")
#define MBAR_WAIT(a, ph) do {                                               \
    uint32_t _m = (a), _p = (ph), _d;                                       \
    asm volatile("{\n\t.reg .pred p;\n\t"                                   \
        "mbarrier.try_wait.parity.acquire.cta.shared::cta.b64 p, [%1], %2;\n\t" \
        "selp.b32 %0, 1, 0, p;\n\t}" : "=r"(_d) : "r"(_m), "r"(_p) : "memory"); \
    if (!_d) {                                                              \
        asm volatile("{\n\t.reg .pred P1;\n\tWL%=:\n\t"                     \
            "mbarrier.try_wait.parity.acquire.cta.shared::cta.b64 P1, [%0], %1, 0x989680;\n\t" \
            "@P1 bra.uni WD%=;\n\tbra.uni WL%=;\n\tWD%=:\n\t}"              \
            :: "r"(_m), "r"(_p) : "memory");                                \
    } } while (0)
#define FENCE_ASYNC() asm volatile("fence.proxy.async.shared::cta;" ::: "memory")

__device__ __forceinline__ void bulk_g2s(uint32_t dst, const void* src,
                                         uint32_t bytes, uint32_t mbar) {
    asm volatile(
        "cp.async.bulk.shared::cta.global.mbarrier::complete_tx::bytes "
        "[%0], [%1], %2, [%3];"
        :: "r"(dst), "l"(__cvta_generic_to_global(src)), "r"(bytes), "r"(mbar)
        : "memory");
}
__device__ __forceinline__ void red_add_v4(float* gptr, float4 v) {
    asm volatile("red.global.add.v4.f32 [%0], {%1, %2, %3, %4};"
                 :: "l"(__cvta_generic_to_global(gptr)),
                    "f"(v.x), "f"(v.y), "f"(v.z), "f"(v.w) : "memory");
}

#define LDSM4(r0, r1, r2, r3, addr) asm volatile(                              \
    "ldmatrix.sync.aligned.m8n8.x4.shared.b16 {%0,%1,%2,%3}, [%4];"            \
    : "=r"(r0), "=r"(r1), "=r"(r2), "=r"(r3) : "r"(addr))

#define MMA(c, a0, a1, a2, a3, b0, b1) asm volatile(                           \
    "mma.sync.aligned.m16n8k16.row.col.f32.bf16.bf16.f32 "                     \
    "{%0,%1,%2,%3},{%4,%5,%6,%7},{%8,%9},{%0,%1,%2,%3};"                       \
    : "+f"((c)[0]), "+f"((c)[1]), "+f"((c)[2]), "+f"((c)[3])                   \
    : "r"(a0), "r"(a1), "r"(a2), "r"(a3), "r"(b0), "r"(b1))

__device__ __forceinline__ unsigned mapf(float d) {
    unsigned u = __float_as_uint(d);
    return (u & 0x80000000u) ? ~u : (u | 0x80000000u);
}
__device__ __forceinline__ float unmapf(unsigned x) {
    return (x & 0x80000000u) ? __uint_as_float(x & 0x7fffffffu)
                             : __uint_as_float(~x);
}

// ---------------------------------------------------------------------------
__global__ void enorm_kernel(const float* __restrict__ emb) {
    int w = (blockIdx.x * blockDim.x + threadIdx.x) >> 5;
    int lane = threadIdx.x & 31;
    if (w >= NCODE) return;
    const float4* p = (const float4*)(emb + (size_t)w * DIM);
    float s = 0.0f;
#pragma unroll
    for (int c = 0; c < 2; c++) {
        float4 v = p[lane + 32 * c];
        s += v.x * v.x + v.y * v.y + v.z * v.z + v.w * v.w;
    }
#pragma unroll
    for (int o = 16; o >= 1; o >>= 1) s += __shfl_xor_sync(0xffffffffu, s, o);
    if (lane == 0) g_enorm[w] = s;
}

// prep: fp32 -> bf16 into tile-contiguous layout; also zeroes scratch.
#define AC (N_TOK * DIM / 8)             // 1,048,576
#define BC (NCODE * DIM / 8)             // 32,768
#define ZC (NCODE * DIM / 4)             // 65,536
__global__ void prep_kernel(const float* __restrict__ z, const float* __restrict__ emb) {
    int p = blockIdx.x * blockDim.x + threadIdx.x;
    if (p < AC) {
        int t = p >> 9, w = p & 511;             // tile, chunk-within
        int row = w >> 2, c4 = w & 3;
        int b = t >> 3, kc = t & 7;
        const float* src = z + (size_t)(b * 128 + row) * DIM + kc * 32 + c4 * 8;
        float4 v0 = *(const float4*)src;
        float4 v1 = *(const float4*)(src + 4);
        __nv_bfloat162 o0 = __halves2bfloat162(__float2bfloat16_rn(v0.x), __float2bfloat16_rn(v0.y));
        __nv_bfloat162 o1 = __halves2bfloat162(__float2bfloat16_rn(v0.z), __float2bfloat16_rn(v0.w));
        __nv_bfloat162 o2 = __halves2bfloat162(__float2bfloat16_rn(v1.x), __float2bfloat16_rn(v1.y));
        __nv_bfloat162 o3 = __halves2bfloat162(__float2bfloat16_rn(v1.z), __float2bfloat16_rn(v1.w));
        uint4 pack = {*(uint32_t*)&o0, *(uint32_t*)&o1, *(uint32_t*)&o2, *(uint32_t*)&o3};
        *(uint4*)(gAt + (size_t)t * TILE_B + row * 80 + c4 * 16) = pack;
    } else if (p < AC + BC) {
        int q = p - AC;
        int t = q >> 9, w = q & 511;
        int row = w >> 2, c4 = w & 3;
        int n = t >> 3, kc = t & 7;
        const float* src = emb + (size_t)(n * 128 + row) * DIM + kc * 32 + c4 * 8;
        float4 v0 = *(const float4*)src;
        float4 v1 = *(const float4*)(src + 4);
        __nv_bfloat162 o0 = __halves2bfloat162(__float2bfloat16_rn(v0.x), __float2bfloat16_rn(v0.y));
        __nv_bfloat162 o1 = __halves2bfloat162(__float2bfloat16_rn(v0.z), __float2bfloat16_rn(v0.w));
        __nv_bfloat162 o2 = __halves2bfloat162(__float2bfloat16_rn(v1.x), __float2bfloat16_rn(v1.y));
        __nv_bfloat162 o3 = __halves2bfloat162(__float2bfloat16_rn(v1.z), __float2bfloat16_rn(v1.w));
        uint4 pack = {*(uint32_t*)&o0, *(uint32_t*)&o1, *(uint32_t*)&o2, *(uint32_t*)&o3};
        *(uint4*)(gBt + (size_t)t * TILE_B + row * 80 + c4 * 16) = pack;
    } else {
        int zi = p - AC - BC;
        if (zi >= ZC) return;
        ((float4*)g_esum)[zi] = make_float4(0.f, 0.f, 0.f, 0.f);
        if (zi < NCODE / 4) ((float4*)g_counts)[zi] = make_float4(0.f, 0.f, 0.f, 0.f);
        if (zi == 0) g_loss = 0.0f;
    }
}

// ---------------------------------------------------------------------------
// Main: A (all 8 k-chunks, 80 KB) resident in smem, loaded once; B streamed
// through a 2-stage bulk-copy ring. HMMA + windowed candidate collection.
// ---------------------------------------------------------------------------
#define SM_A     0                       // 8 x 10240 = 81920
#define SM_B     81920                   // 2 stages x 10240 = 20480
#define SM_EN    102400                  // 4 KB
#define SM_MINU  106496                  // 128 x u32
#define SM_CNT   107008                  // 128 x int
#define SM_MBAR  107520                  // A mbar + 2 B mbars = 24 B
#define SM_TOTAL 107584

__global__ __launch_bounds__(256, 2)
void vq_main_kernel() {
    extern __shared__ char smem[];
    const uint32_t sb = smem_u32(smem);
    const int tid  = threadIdx.x;
    const int lane = tid & 31;
    const int wid  = tid >> 5;
    const int wm   = wid >> 2;           // 0..1  (M half)
    const int wn   = wid & 3;            // 0..3  (N quarter, 32 cols)
    const int rowBase = blockIdx.x * 128;

    float*    sEnorm = (float*)(smem + SM_EN);
    unsigned* sMinU  = (unsigned*)(smem + SM_MINU);
    int*      sCnt   = (int*)(smem + SM_CNT);

#pragma unroll
    for (int i = 0; i < 4; i++) sEnorm[tid + i * 256] = g_enorm[tid + i * 256];
    if (tid < 128) { sMinU[tid] = 0xffffffffu; sCnt[tid] = 0; }
    if (tid == 0) {
        MBAR_INIT(sb + SM_MBAR, 1);          // A barrier
        MBAR_INIT(sb + SM_MBAR + 8, 1);      // B stage 0
        MBAR_INIT(sb + SM_MBAR + 16, 1);     // B stage 1
    }
    __syncthreads();
    FENCE_ASYNC();

#define ISSUE_B(j) do {                                                        \
    int _s = (j) & 1;                                                          \
    uint32_t _mb = sb + SM_MBAR + 8 + _s * 8;                                  \
    MBAR_EXPECT_TX(_mb, TILE_B);                                               \
    bulk_g2s(sb + SM_B + _s * TILE_B, gBt + (size_t)(j) * TILE_B, TILE_B, _mb);\
} while (0)

    if (tid == 0) {
        // A: all 8 k-chunk tiles, one barrier
        MBAR_EXPECT_TX(sb + SM_MBAR, 8 * TILE_B);
#pragma unroll
        for (int kc = 0; kc < 8; kc++)
            bulk_g2s(sb + SM_A + kc * TILE_B,
                     gAt + (size_t)(blockIdx.x * 8 + kc) * TILE_B,
                     TILE_B, sb + SM_MBAR);
        ISSUE_B(0);
    }
    MBAR_WAIT(sb + SM_MBAR, 0);              // A resident

    // ldmatrix per-lane address offsets (bytes), row stride 80B
    const uint32_t aOff = (uint32_t)((wm * 64 + (lane & 15)) * 80 + (lane >> 4) * 16);
    const uint32_t bOff = (uint32_t)((wn * 32 + (lane & 7) + ((lane >> 4) << 3)) * 80
                                     + ((lane >> 3) & 1) * 16);

    float acc[4][4][4];
#pragma unroll
    for (int m = 0; m < 4; m++)
#pragma unroll
        for (int nf = 0; nf < 4; nf++)
#pragma unroll
            for (int v = 0; v < 4; v++) acc[m][nf][v] = 0.0f;

    // smem counter, direct global store of packed (dist, code)
#define EMIT(dd, cc, rloc) do {                                                \
    int _p = atomicAdd(&sCnt[rloc], 1);                                        \
    if (_p < CAP)                                                              \
        g_cand64[(size_t)(rowBase + (rloc)) * CAP + _p] =                      \
            ((unsigned long long)mapf(dd) << 32) | (unsigned)(cc);             \
} while (0)

    for (int it = 0; it < 64; it++) {
        MBAR_WAIT(sb + SM_MBAR + 8 + (it & 1) * 8, (it >> 1) & 1);
        // other stage was consumed before the barrier at the end of it-1
        if (tid == 0 && it + 1 < 64) ISSUE_B(it + 1);

        const uint32_t aT = sb + SM_A + (it & 7) * TILE_B + aOff;
        const uint32_t bB = sb + SM_B + (it & 1) * TILE_B + bOff;

#pragma unroll
        for (int s = 0; s < 2; s++) {                    // two k16 steps
            uint32_t b[4][2];
#pragma unroll
            for (int q = 0; q < 2; q++) {
                uint32_t r0, r1, r2, r3;
                LDSM4(r0, r1, r2, r3, bB + q * 1280 + s * 32);
                b[2 * q][0] = r0; b[2 * q][1] = r1;
                b[2 * q + 1][0] = r2; b[2 * q + 1][1] = r3;
            }
#pragma unroll
            for (int m = 0; m < 4; m++) {
                uint32_t a0, a1, a2, a3;
                LDSM4(a0, a1, a2, a3, aT + m * 1280 + s * 32);
#pragma unroll
                for (int nf = 0; nf < 4; nf++)
                    MMA(acc[m][nf], a0, a1, a2, a3, b[nf][0], b[nf][1]);
            }
        }

        if ((it & 7) == 7) {                             // end of n-tile
            const int n = it >> 3;
            const int colB = n * 128 + wn * 32 + 2 * (lane & 3);
            // pass 1: settle per-row approx min
#pragma unroll
            for (int m = 0; m < 4; m++) {
                int r0 = wm * 64 + m * 16 + (lane >> 2);
                float bd0 = 3.4e38f, bd1 = 3.4e38f;
#pragma unroll
                for (int nf = 0; nf < 4; nf++) {
                    float2 en = *(const float2*)&sEnorm[colB + nf * 8];
                    bd0 = fminf(bd0, fminf(en.x - 2.0f * acc[m][nf][0],
                                           en.y - 2.0f * acc[m][nf][1]));
                    bd1 = fminf(bd1, fminf(en.x - 2.0f * acc[m][nf][2],
                                           en.y - 2.0f * acc[m][nf][3]));
                }
#pragma unroll
                for (int off = 1; off <= 2; off <<= 1) {
                    bd0 = fminf(bd0, __shfl_xor_sync(0xffffffffu, bd0, off));
                    bd1 = fminf(bd1, __shfl_xor_sync(0xffffffffu, bd1, off));
                }
                if ((lane & 3) == 0) {
                    atomicMin(&sMinU[r0], mapf(bd0));
                    atomicMin(&sMinU[r0 + 8], mapf(bd1));
                }
            }
            __syncthreads();
            // pass 2: emit candidates within TAU of settled min
#pragma unroll
            for (int m = 0; m < 4; m++) {
                int r0 = wm * 64 + m * 16 + (lane >> 2);
                float thr0 = unmapf(sMinU[r0]) + TAU;
                float thr1 = unmapf(sMinU[r0 + 8]) + TAU;
#pragma unroll
                for (int nf = 0; nf < 4; nf++) {
                    float2 en = *(const float2*)&sEnorm[colB + nf * 8];
                    float d0 = en.x - 2.0f * acc[m][nf][0];
                    float d1 = en.y - 2.0f * acc[m][nf][1];
                    float d2 = en.x - 2.0f * acc[m][nf][2];
                    float d3 = en.y - 2.0f * acc[m][nf][3];
                    int c0 = colB + nf * 8;
                    if (d0 < thr0) EMIT(d0, c0,     r0);
                    if (d1 < thr0) EMIT(d1, c0 + 1, r0);
                    if (d2 < thr1) EMIT(d2, c0,     r0 + 8);
                    if (d3 < thr1) EMIT(d3, c0 + 1, r0 + 8);
                    acc[m][nf][0] = 0.0f; acc[m][nf][1] = 0.0f;
                    acc[m][nf][2] = 0.0f; acc[m][nf][3] = 0.0f;
                }
            }
        }
        __syncthreads();                                 // stage consumed
    }

    // dump counts (clamped) + final per-row approx min
    if (tid < 128) {
        int c = sCnt[tid];
        g_cnt[rowBase + tid]  = c > CAP ? CAP : c;
        g_minu[rowBase + tid] = sMinU[tid];
    }
}

// ---------------------------------------------------------------------------
// Refine + output kernel: grid N_TOK/16, 256 threads.
// ---------------------------------------------------------------------------
__global__ __launch_bounds__(256, 8)
void outref_kernel(const float* __restrict__ z, const float* __restrict__ emb,
                   float* __restrict__ out) {
    __shared__ int   sBestC[16];
    __shared__ float sRed[8];
    const int tid  = threadIdx.x;
    const int lane = tid & 31;
    const int wid  = tid >> 5;
    const int rowBase = blockIdx.x * 16;

#pragma unroll
    for (int rr = 0; rr < 2; rr++) {
        int r = rowBase + wid * 2 + rr;
        int cnt = g_cnt[r];
        unsigned mthr = mapf(unmapf(g_minu[r]) + TAU2);
        const float* zr = z + (size_t)r * DIM;
        float zv[8];
#pragma unroll
        for (int j = 0; j < 8; j++) zv[j] = zr[lane + 32 * j];
        float bestd = 3.4e38f; int bestc = 0x7fffffff;
        for (int base = 0; base < cnt; base += 32) {     // almost always 1 pass
            int ci = base + lane;
            unsigned long long pk = ~0ull;
            if (ci < cnt) pk = g_cand64[(size_t)r * CAP + ci];  // coalesced
            bool pass = (ci < cnt) && ((unsigned)(pk >> 32) <= mthr);
            unsigned msk = __ballot_sync(0xffffffffu, pass);
            while (msk) {                                // survivors: ~1-2
                int src = __ffs(msk) - 1; msk &= msk - 1;
                unsigned long long cpk = __shfl_sync(0xffffffffu, pk, src);
                int c = (int)(unsigned)(cpk & 0xffffffffull);
                const float* er = emb + (size_t)c * DIM;
                float dot = 0.0f;
#pragma unroll
                for (int j = 0; j < 8; j++) dot += zv[j] * er[lane + 32 * j];
#pragma unroll
                for (int o = 16; o >= 1; o >>= 1)
                    dot += __shfl_xor_sync(0xffffffffu, dot, o);
                float dd = g_enorm[c] - 2.0f * dot;
                if (dd < bestd || (dd == bestd && c < bestc)) { bestd = dd; bestc = c; }
            }
        }
        if (lane == 0) {
            sBestC[wid * 2 + rr] = bestc;
            out[OFF_IDX + r] = (float)bestc;
            atomicAdd(&g_counts[bestc], 1.0f);
        }
    }
    __syncthreads();

    // phase B: 4 row-groups x 64 column-threads, float4 everywhere
    float lossAcc = 0.0f;
    const int c4 = (tid & 63) * 4;
    const int rg = tid >> 6;
#pragma unroll
    for (int k = 0; k < 4; k++) {
        int rr   = rg * 4 + k;
        int code = sBestC[rr];
        int row  = rowBase + rr;
        float4 e  = *(const float4*)(emb + (size_t)code * DIM + c4);
        float4 zv = *(const float4*)(z + (size_t)row * DIM + c4);
        float4 df = make_float4(e.x - zv.x, e.y - zv.y, e.z - zv.z, e.w - zv.w);
        float4 q  = make_float4(zv.x + df.x, zv.y + df.y, zv.z + df.z, zv.w + df.w);
        *(float4*)(out + OFF_ZQ + (size_t)row * DIM + c4) = q;
        lossAcc += df.x * df.x + df.y * df.y + df.z * df.z + df.w * df.w;
        red_add_v4(&g_esum[code * DIM + c4], zv);
    }
#pragma unroll
    for (int o = 16; o >= 1; o >>= 1) lossAcc += __shfl_xor_sync(0xffffffffu, lossAcc, o);
    if (lane == 0) sRed[wid] = lossAcc;
    __syncthreads();
    if (tid < 8) {
        float v = sRed[tid];
#pragma unroll
        for (int o = 4; o >= 1; o >>= 1) v += __shfl_xor_sync(0xffu, v, o, 8);
        if (tid == 0) atomicAdd(&g_loss, v);
    }
}

// ---------------------------------------------------------------------------
__global__ void fin1_kernel(const float* __restrict__ cs, float* __restrict__ out) {
    int k = threadIdx.x;
    float ncs = cs[k] * 0.99f + 0.01f * g_counts[k];
    out[OFF_CS + k] = ncs;
    __shared__ float red[32];
    float v = ncs;
#pragma unroll
    for (int o = 16; o >= 1; o >>= 1) v += __shfl_xor_sync(0xffffffffu, v, o);
    if ((k & 31) == 0) red[k >> 5] = v;
    __syncthreads();
    if (k < 32) {
        float t = red[k];
#pragma unroll
        for (int o = 16; o >= 1; o >>= 1) t += __shfl_xor_sync(0xffffffffu, t, o);
        if (k == 0) {
            g_nsum = t;
            out[OFF_LOSS] = 0.25f * g_loss / (float)(N_TOK * DIM);
        }
    }
}

__global__ void fin2_kernel(const float* __restrict__ avg, float* __restrict__ out) {
    int i = blockIdx.x * blockDim.x + threadIdx.x;
    float navg = avg[i] * 0.99f + 0.01f * g_esum[i];
    out[OFF_AVG + i] = navg;
    int k = i >> 8;
    float ncs = out[OFF_CS + k];
    float csn = (ncs + 1e-6f) / (g_nsum + (float)NCODE * 1e-6f);
    out[OFF_EMB + i] = navg / csn;
}

// ---------------------------------------------------------------------------
extern "C" void kernel_launch(void* const* d_in, const int* in_sizes, int n_in,
                              void* d_out, int out_size) {
    const float* z   = (const float*)d_in[0];
    const float* emb = (const float*)d_in[1];
    const float* cs  = (const float*)d_in[2];
    const float* avg = (const float*)d_in[3];
    float* out = (float*)d_out;

    cudaFuncSetAttribute(vq_main_kernel,
                         cudaFuncAttributeMaxDynamicSharedMemorySize, SM_TOTAL);

    enorm_kernel<<<(NCODE * 32) / 256, 256>>>(emb);
    prep_kernel<<<(AC + BC + ZC + 255) / 256, 256>>>(z, emb);
    vq_main_kernel<<<N_TOK / 128, 256, SM_TOTAL>>>();
    outref_kernel<<<N_TOK / 16, 256>>>(z, emb, out);
    fin1_kernel<<<1, 1024>>>(cs, out);
    fin2_kernel<<<(NCODE * DIM) / 256, 256>>>(avg, out);
}

// round 15
// speedup vs baseline: 1.4604x; 1.0277x over previous
#include <cuda_runtime.h>
#include <cuda_bf16.h>
#include <cstdint>

#define N_TOK 32768
#define DIM   256
#define NCODE 1024
#define TAU   3.0f
#define TAU2  0.75f
#define CAP   48

// d_out layout (float32): z_q_st, loss, indices, new_cluster_size,
// new_embedding_avg, new_embedding
#define OFF_ZQ   0
#define OFF_LOSS (N_TOK * DIM)
#define OFF_IDX  (OFF_LOSS + 1)
#define OFF_CS   (OFF_IDX + N_TOK)
#define OFF_AVG  (OFF_CS + NCODE)
#define OFF_EMB  (OFF_AVG + NCODE * DIM)

#define TILE_B   10240                   // 128 rows x 80 B (64 B data + pad)

__device__ __align__(16) float g_enorm[NCODE];
__device__ float g_counts[NCODE];
__device__ __align__(16) float g_esum[NCODE * DIM];
__device__ float g_loss;
__device__ float g_nsum;
// tile-contiguous bf16 images: gAt[block][kc][row*80 + c*2], gBt[n][kc][...]
__device__ __align__(16) uint8_t gAt[(N_TOK / 128) * 8 * TILE_B];   // 21 MB
__device__ __align__(16) uint8_t gBt[(NCODE / 128) * 8 * TILE_B];   // 655 KB
__device__ int g_cnt[N_TOK];
__device__ unsigned g_minu[N_TOK];
__device__ unsigned long long g_cand64[N_TOK * CAP];   // (mapped dist, code)

// ---------------------------------------------------------------------------
__device__ __forceinline__ uint32_t smem_u32(const void* p) {
    uint32_t a;
    asm("{ .reg .u64 t; cvta.to.shared.u64 t, %1; cvt.u32.u64 %0, t; }"
        : "=r"(a) : "l"(p));
    return a;
}
#define MBAR_INIT(a, c) asm volatile("mbarrier.init.shared.b64 [%0], %1;" \
    :: "r"(a), "r"(c) : "memory")
#define MBAR_EXPECT_TX(a, b) asm volatile(                                    \
    "mbarrier.arrive.expect_tx.shared.b64 _, [%0], %1;"                       \
    :: "r"(a), "r"(b) : "memory")
#define MBAR_WAIT(a, ph) do {                                               \
    uint32_t _m = (a), _p = (ph), _d;                                       \
    asm volatile("{\n\t.reg .pred p;\n\t"                                   \
        "mbarrier.try_wait.parity.acquire.cta.shared::cta.b64 p, [%1], %2;\n\t" \
        "selp.b32 %0, 1, 0, p;\n\t}" : "=r"(_d) : "r"(_m), "r"(_p) : "memory"); \
    if (!_d) {                                                              \
        asm volatile("{\n\t.reg .pred P1;\n\tWL%=:\n\t"                     \
            "mbarrier.try_wait.parity.acquire.cta.shared::cta.b64 P1, [%0], %1, 0x989680;\n\t" \
            "@P1 bra.uni WD%=;\n\tbra.uni WL%=;\n\tWD%=:\n\t}"              \
            :: "r"(_m), "r"(_p) : "memory");                                \
    } } while (0)
#define FENCE_ASYNC() asm volatile("fence.proxy.async.shared::cta;" ::: "memory")

__device__ __forceinline__ void bulk_g2s(uint32_t dst, const void* src,
                                         uint32_t bytes, uint32_t mbar) {
    asm volatile(
        "cp.async.bulk.shared::cta.global.mbarrier::complete_tx::bytes "
        "[%0], [%1], %2, [%3];"
        :: "r"(dst), "l"(__cvta_generic_to_global(src)), "r"(bytes), "r"(mbar)
        : "memory");
}
__device__ __forceinline__ void red_add_v4(float* gptr, float4 v) {
    asm volatile("red.global.add.v4.f32 [%0], {%1, %2, %3, %4};"
                 :: "l"(__cvta_generic_to_global(gptr)),
                    "f"(v.x), "f"(v.y), "f"(v.z), "f"(v.w) : "memory");
}

#define LDSM4(r0, r1, r2, r3, addr) asm volatile(                              \
    "ldmatrix.sync.aligned.m8n8.x4.shared.b16 {%0,%1,%2,%3}, [%4];"            \
    : "=r"(r0), "=r"(r1), "=r"(r2), "=r"(r3) : "r"(addr))

#define MMA(c, a0, a1, a2, a3, b0, b1) asm volatile(                           \
    "mma.sync.aligned.m16n8k16.row.col.f32.bf16.bf16.f32 "                     \
    "{%0,%1,%2,%3},{%4,%5,%6,%7},{%8,%9},{%0,%1,%2,%3};"                       \
    : "+f"((c)[0]), "+f"((c)[1]), "+f"((c)[2]), "+f"((c)[3])                   \
    : "r"(a0), "r"(a1), "r"(a2), "r"(a3), "r"(b0), "r"(b1))

__device__ __forceinline__ unsigned mapf(float d) {
    unsigned u = __float_as_uint(d);
    return (u & 0x80000000u) ? ~u : (u | 0x80000000u);
}
__device__ __forceinline__ float unmapf(unsigned x) {
    return (x & 0x80000000u) ? __uint_as_float(x & 0x7fffffffu)
                             : __uint_as_float(~x);
}

// ---------------------------------------------------------------------------
// prep: fp32 -> bf16 tile-contiguous images + zero scratch + enorm (fused).
#define AC (N_TOK * DIM / 8)             // 1,048,576
#define BC (NCODE * DIM / 8)             // 32,768
#define ZC (NCODE * DIM / 4)             // 65,536
#define EC (NCODE * 32)                  // 32,768 (one warp per code)
__global__ void prep_kernel(const float* __restrict__ z, const float* __restrict__ emb) {
    int p = blockIdx.x * blockDim.x + threadIdx.x;
    if (p < AC) {
        int t = p >> 9, w = p & 511;             // tile, chunk-within
        int row = w >> 2, c4 = w & 3;
        int b = t >> 3, kc = t & 7;
        const float* src = z + (size_t)(b * 128 + row) * DIM + kc * 32 + c4 * 8;
        float4 v0 = *(const float4*)src;
        float4 v1 = *(const float4*)(src + 4);
        __nv_bfloat162 o0 = __halves2bfloat162(__float2bfloat16_rn(v0.x), __float2bfloat16_rn(v0.y));
        __nv_bfloat162 o1 = __halves2bfloat162(__float2bfloat16_rn(v0.z), __float2bfloat16_rn(v0.w));
        __nv_bfloat162 o2 = __halves2bfloat162(__float2bfloat16_rn(v1.x), __float2bfloat16_rn(v1.y));
        __nv_bfloat162 o3 = __halves2bfloat162(__float2bfloat16_rn(v1.z), __float2bfloat16_rn(v1.w));
        uint4 pack = {*(uint32_t*)&o0, *(uint32_t*)&o1, *(uint32_t*)&o2, *(uint32_t*)&o3};
        *(uint4*)(gAt + (size_t)t * TILE_B + row * 80 + c4 * 16) = pack;
    } else if (p < AC + BC) {
        int q = p - AC;
        int t = q >> 9, w = q & 511;
        int row = w >> 2, c4 = w & 3;
        const float* src = emb + (size_t)((t >> 3) * 128 + row) * DIM + (t & 7) * 32 + c4 * 8;
        float4 v0 = *(const float4*)src;
        float4 v1 = *(const float4*)(src + 4);
        __nv_bfloat162 o0 = __halves2bfloat162(__float2bfloat16_rn(v0.x), __float2bfloat16_rn(v0.y));
        __nv_bfloat162 o1 = __halves2bfloat162(__float2bfloat16_rn(v0.z), __float2bfloat16_rn(v0.w));
        __nv_bfloat162 o2 = __halves2bfloat162(__float2bfloat16_rn(v1.x), __float2bfloat16_rn(v1.y));
        __nv_bfloat162 o3 = __halves2bfloat162(__float2bfloat16_rn(v1.z), __float2bfloat16_rn(v1.w));
        uint4 pack = {*(uint32_t*)&o0, *(uint32_t*)&o1, *(uint32_t*)&o2, *(uint32_t*)&o3};
        *(uint4*)(gBt + (size_t)t * TILE_B + row * 80 + c4 * 16) = pack;
    } else if (p < AC + BC + ZC) {
        int zi = p - AC - BC;
        ((float4*)g_esum)[zi] = make_float4(0.f, 0.f, 0.f, 0.f);
        if (zi < NCODE / 4) ((float4*)g_counts)[zi] = make_float4(0.f, 0.f, 0.f, 0.f);
        if (zi == 0) g_loss = 0.0f;
    } else {
        int q2 = p - AC - BC - ZC;               // enorm: one warp per code
        int w = q2 >> 5, lane = q2 & 31;
        const float4* pe = (const float4*)(emb + (size_t)w * DIM);
        float s = 0.0f;
#pragma unroll
        for (int c = 0; c < 2; c++) {
            float4 v = pe[lane + 32 * c];
            s += v.x * v.x + v.y * v.y + v.z * v.z + v.w * v.w;
        }
#pragma unroll
        for (int o = 16; o >= 1; o >>= 1) s += __shfl_xor_sync(0xffffffffu, s, o);
        if (lane == 0) g_enorm[w] = s;
    }
}

// ---------------------------------------------------------------------------
// Main: bulk-copy-fed bf16 HMMA approx GEMM + windowed candidate collection.
// (R12 structure: 4-stage A+B ring, early re-arm, smem counters.)
// ---------------------------------------------------------------------------
#define STAGE_SZ 20480                   // A 10240 + B 10240
#define SM_EN    81920                   // 4 KB
#define SM_MINU  86016                   // 128 x u32
#define SM_CNT   86528                   // 128 x int
#define SM_MBAR  87040                   // 4 x 8 B
#define SM_TOTAL 87104

__global__ __launch_bounds__(256, 2)
void vq_main_kernel() {
    extern __shared__ char smem[];
    const uint32_t sb = smem_u32(smem);
    const int tid  = threadIdx.x;
    const int lane = tid & 31;
    const int wid  = tid >> 5;
    const int wm   = wid >> 2;           // 0..1  (M half)
    const int wn   = wid & 3;            // 0..3  (N quarter, 32 cols)
    const int rowBase = blockIdx.x * 128;

    float*    sEnorm = (float*)(smem + SM_EN);
    unsigned* sMinU  = (unsigned*)(smem + SM_MINU);
    int*      sCnt   = (int*)(smem + SM_CNT);

#pragma unroll
    for (int i = 0; i < 4; i++) sEnorm[tid + i * 256] = g_enorm[tid + i * 256];
    if (tid < 128) { sMinU[tid] = 0xffffffffu; sCnt[tid] = 0; }
    if (tid == 0) {
#pragma unroll
        for (int s = 0; s < 4; s++) MBAR_INIT(sb + SM_MBAR + s * 8, 1);
    }
    __syncthreads();
    FENCE_ASYNC();

    // producer: j = n*8 + kc
#define ISSUE(j) do {                                                          \
    int _s = (j) & 3;                                                          \
    uint32_t _st = sb + _s * STAGE_SZ;                                         \
    uint32_t _mb = sb + SM_MBAR + _s * 8;                                      \
    MBAR_EXPECT_TX(_mb, STAGE_SZ);                                             \
    bulk_g2s(_st, gAt + (size_t)(blockIdx.x * 8 + ((j) & 7)) * TILE_B,         \
             TILE_B, _mb);                                                     \
    bulk_g2s(_st + TILE_B, gBt + (size_t)(j) * TILE_B, TILE_B, _mb);           \
} while (0)

    if (tid == 0) { ISSUE(0); ISSUE(1); ISSUE(2); }

    // ldmatrix per-lane address offsets (bytes), row stride 80B
    const uint32_t aOff = (uint32_t)((wm * 64 + (lane & 15)) * 80 + (lane >> 4) * 16);
    const uint32_t bOff = (uint32_t)((wn * 32 + (lane & 7) + ((lane >> 4) << 3)) * 80
                                     + ((lane >> 3) & 1) * 16);

    float acc[4][4][4];
#pragma unroll
    for (int m = 0; m < 4; m++)
#pragma unroll
        for (int nf = 0; nf < 4; nf++)
#pragma unroll
            for (int v = 0; v < 4; v++) acc[m][nf][v] = 0.0f;

    // smem counter, direct global store of packed (dist, code)
#define EMIT(dd, cc, rloc) do {                                                \
    int _p = atomicAdd(&sCnt[rloc], 1);                                        \
    if (_p < CAP)                                                              \
        g_cand64[(size_t)(rowBase + (rloc)) * CAP + _p] =                      \
            ((unsigned long long)mapf(dd) << 32) | (unsigned)(cc);             \
} while (0)

    for (int it = 0; it < 64; it++) {
        MBAR_WAIT(sb + SM_MBAR + (it & 3) * 8, (it >> 2) & 1);
        if (tid == 0 && it + 3 < 64) ISSUE(it + 3);

        const uint32_t stBase = sb + (it & 3) * STAGE_SZ;
        const uint32_t aB = stBase + aOff;
        const uint32_t bB = stBase + TILE_B + bOff;

#pragma unroll
        for (int s = 0; s < 2; s++) {                    // two k16 steps
            uint32_t b[4][2];
#pragma unroll
            for (int q = 0; q < 2; q++) {
                uint32_t r0, r1, r2, r3;
                LDSM4(r0, r1, r2, r3, bB + q * 1280 + s * 32);
                b[2 * q][0] = r0; b[2 * q][1] = r1;
                b[2 * q + 1][0] = r2; b[2 * q + 1][1] = r3;
            }
#pragma unroll
            for (int m = 0; m < 4; m++) {
                uint32_t a0, a1, a2, a3;
                LDSM4(a0, a1, a2, a3, aB + m * 1280 + s * 32);
#pragma unroll
                for (int nf = 0; nf < 4; nf++)
                    MMA(acc[m][nf], a0, a1, a2, a3, b[nf][0], b[nf][1]);
            }
        }

        if ((it & 7) == 7) {                             // end of n-tile
            const int n = it >> 3;
            const int colB = n * 128 + wn * 32 + 2 * (lane & 3);
            // pass 1: settle per-row approx min
#pragma unroll
            for (int m = 0; m < 4; m++) {
                int r0 = wm * 64 + m * 16 + (lane >> 2);
                float bd0 = 3.4e38f, bd1 = 3.4e38f;
#pragma unroll
                for (int nf = 0; nf < 4; nf++) {
                    float2 en = *(const float2*)&sEnorm[colB + nf * 8];
                    bd0 = fminf(bd0, fminf(en.x - 2.0f * acc[m][nf][0],
                                           en.y - 2.0f * acc[m][nf][1]));
                    bd1 = fminf(bd1, fminf(en.x - 2.0f * acc[m][nf][2],
                                           en.y - 2.0f * acc[m][nf][3]));
                }
#pragma unroll
                for (int off = 1; off <= 2; off <<= 1) {
                    bd0 = fminf(bd0, __shfl_xor_sync(0xffffffffu, bd0, off));
                    bd1 = fminf(bd1, __shfl_xor_sync(0xffffffffu, bd1, off));
                }
                if ((lane & 3) == 0) {
                    atomicMin(&sMinU[r0], mapf(bd0));
                    atomicMin(&sMinU[r0 + 8], mapf(bd1));
                }
            }
            __syncthreads();
            // pass 2: emit candidates within TAU of settled min
#pragma unroll
            for (int m = 0; m < 4; m++) {
                int r0 = wm * 64 + m * 16 + (lane >> 2);
                float thr0 = unmapf(sMinU[r0]) + TAU;
                float thr1 = unmapf(sMinU[r0 + 8]) + TAU;
#pragma unroll
                for (int nf = 0; nf < 4; nf++) {
                    float2 en = *(const float2*)&sEnorm[colB + nf * 8];
                    float d0 = en.x - 2.0f * acc[m][nf][0];
                    float d1 = en.y - 2.0f * acc[m][nf][1];
                    float d2 = en.x - 2.0f * acc[m][nf][2];
                    float d3 = en.y - 2.0f * acc[m][nf][3];
                    int c0 = colB + nf * 8;
                    if (d0 < thr0) EMIT(d0, c0,     r0);
                    if (d1 < thr0) EMIT(d1, c0 + 1, r0);
                    if (d2 < thr1) EMIT(d2, c0,     r0 + 8);
                    if (d3 < thr1) EMIT(d3, c0 + 1, r0 + 8);
                    acc[m][nf][0] = 0.0f; acc[m][nf][1] = 0.0f;
                    acc[m][nf][2] = 0.0f; acc[m][nf][3] = 0.0f;
                }
            }
        }
        __syncthreads();                                 // stage consumed
    }

    // dump counts (clamped) + final per-row approx min
    if (tid < 128) {
        int c = sCnt[tid];
        g_cnt[rowBase + tid]  = c > CAP ? CAP : c;
        g_minu[rowBase + tid] = sMinU[tid];
    }
}

// ---------------------------------------------------------------------------
// Refine + output kernel: grid N_TOK/16, 256 threads.
// Phase A: both of the warp's rows processed concurrently (2x ILP).
//   - one coalesced load of each row's candidate words, TAU2 ballot
//   - single survivor (& cnt<=32)  =>  it IS the exact argmin: no dot needed
//   - multi survivors: interleaved warp-cooperative exact fp32 dots
// Phase B: vectorized float4 z_q_st / loss / esum.
// ---------------------------------------------------------------------------
__global__ __launch_bounds__(256, 8)
void outref_kernel(const float* __restrict__ z, const float* __restrict__ emb,
                   float* __restrict__ out) {
    __shared__ int   sBestC[16];
    __shared__ float sRed[8];
    const int tid  = threadIdx.x;
    const int lane = tid & 31;
    const int wid  = tid >> 5;
    const int rowBase = blockIdx.x * 16;

    {
        const int r0 = rowBase + wid * 2;
        const int r1 = r0 + 1;
        int cnt0 = g_cnt[r0], cnt1 = g_cnt[r1];
        unsigned mthr0 = mapf(unmapf(g_minu[r0]) + TAU2);
        unsigned mthr1 = mapf(unmapf(g_minu[r1]) + TAU2);
        const float* zr0 = z + (size_t)r0 * DIM;
        const float* zr1 = z + (size_t)r1 * DIM;
        float zv0[8], zv1[8];
#pragma unroll
        for (int j = 0; j < 8; j++) { zv0[j] = zr0[lane + 32 * j]; zv1[j] = zr1[lane + 32 * j]; }

        unsigned long long pk0 = ~0ull, pk1 = ~0ull;
        if (lane < cnt0) pk0 = g_cand64[(size_t)r0 * CAP + lane];
        if (lane < cnt1) pk1 = g_cand64[(size_t)r1 * CAP + lane];
        unsigned msk0 = __ballot_sync(0xffffffffu,
                            lane < cnt0 && (unsigned)(pk0 >> 32) <= mthr0);
        unsigned msk1 = __ballot_sync(0xffffffffu,
                            lane < cnt1 && (unsigned)(pk1 >> 32) <= mthr1);

        float bestd0 = 3.4e38f, bestd1 = 3.4e38f;
        int   bestc0 = 0x7fffffff, bestc1 = 0x7fffffff;

        // single-survivor shortcut (only valid if all candidates were seen)
        if (cnt0 <= 32 && __popc(msk0) == 1) {
            int src = __ffs(msk0) - 1;
            bestc0 = (int)(unsigned)(__shfl_sync(0xffffffffu, pk0, src) & 0xffffffffull);
            bestd0 = -3.4e38f;                   // locked
            msk0 = 0;
        }
        if (cnt1 <= 32 && __popc(msk1) == 1) {
            int src = __ffs(msk1) - 1;
            bestc1 = (int)(unsigned)(__shfl_sync(0xffffffffu, pk1, src) & 0xffffffffull);
            bestd1 = -3.4e38f;
            msk1 = 0;
        }

        // interleaved refinement of remaining survivors (both rows at once)
        while (msk0 | msk1) {
            int c0 = 0, c1 = 0; bool a0 = false, a1 = false;
            if (msk0) {
                int src = __ffs(msk0) - 1; msk0 &= msk0 - 1;
                c0 = (int)(unsigned)(__shfl_sync(0xffffffffu, pk0, src) & 0xffffffffull);
                a0 = true;
            }
            if (msk1) {
                int src = __ffs(msk1) - 1; msk1 &= msk1 - 1;
                c1 = (int)(unsigned)(__shfl_sync(0xffffffffu, pk1, src) & 0xffffffffull);
                a1 = true;
            }
            const float* e0 = emb + (size_t)c0 * DIM;
            const float* e1 = emb + (size_t)c1 * DIM;
            float dot0 = 0.0f, dot1 = 0.0f;
#pragma unroll
            for (int j = 0; j < 8; j++) {
                dot0 += zv0[j] * e0[lane + 32 * j];
                dot1 += zv1[j] * e1[lane + 32 * j];
            }
#pragma unroll
            for (int o = 16; o >= 1; o >>= 1) {
                dot0 += __shfl_xor_sync(0xffffffffu, dot0, o);
                dot1 += __shfl_xor_sync(0xffffffffu, dot1, o);
            }
            if (a0) {
                float dd = g_enorm[c0] - 2.0f * dot0;
                if (dd < bestd0 || (dd == bestd0 && c0 < bestc0)) { bestd0 = dd; bestc0 = c0; }
            }
            if (a1) {
                float dd = g_enorm[c1] - 2.0f * dot1;
                if (dd < bestd1 || (dd == bestd1 && c1 < bestc1)) { bestd1 = dd; bestc1 = c1; }
            }
        }

        // rare tail: candidates beyond the first 32 (cnt > 32)
        for (int base = 32; base < cnt0; base += 32) {
            int ci = base + lane;
            unsigned long long pk = ~0ull;
            if (ci < cnt0) pk = g_cand64[(size_t)r0 * CAP + ci];
            bool pass = (ci < cnt0) && ((unsigned)(pk >> 32) <= mthr0);
            unsigned msk = __ballot_sync(0xffffffffu, pass);
            while (msk) {
                int src = __ffs(msk) - 1; msk &= msk - 1;
                int c = (int)(unsigned)(__shfl_sync(0xffffffffu, pk, src) & 0xffffffffull);
                const float* er = emb + (size_t)c * DIM;
                float dot = 0.0f;
#pragma unroll
                for (int j = 0; j < 8; j++) dot += zv0[j] * er[lane + 32 * j];
#pragma unroll
                for (int o = 16; o >= 1; o >>= 1) dot += __shfl_xor_sync(0xffffffffu, dot, o);
                float dd = g_enorm[c] - 2.0f * dot;
                if (dd < bestd0 || (dd == bestd0 && c < bestc0)) { bestd0 = dd; bestc0 = c; }
            }
        }
        for (int base = 32; base < cnt1; base += 32) {
            int ci = base + lane;
            unsigned long long pk = ~0ull;
            if (ci < cnt1) pk = g_cand64[(size_t)r1 * CAP + ci];
            bool pass = (ci < cnt1) && ((unsigned)(pk >> 32) <= mthr1);
            unsigned msk = __ballot_sync(0xffffffffu, pass);
            while (msk) {
                int src = __ffs(msk) - 1; msk &= msk - 1;
                int c = (int)(unsigned)(__shfl_sync(0xffffffffu, pk, src) & 0xffffffffull);
                const float* er = emb + (size_t)c * DIM;
                float dot = 0.0f;
#pragma unroll
                for (int j = 0; j < 8; j++) dot += zv1[j] * er[lane + 32 * j];
#pragma unroll
                for (int o = 16; o >= 1; o >>= 1) dot += __shfl_xor_sync(0xffffffffu, dot, o);
                float dd = g_enorm[c] - 2.0f * dot;
                if (dd < bestd1 || (dd == bestd1 && c < bestc1)) { bestd1 = dd; bestc1 = c; }
            }
        }

        if (lane == 0) {
            sBestC[wid * 2]     = bestc0;
            sBestC[wid * 2 + 1] = bestc1;
            out[OFF_IDX + r0] = (float)bestc0;
            out[OFF_IDX + r1] = (float)bestc1;
            atomicAdd(&g_counts[bestc0], 1.0f);
            atomicAdd(&g_counts[bestc1], 1.0f);
        }
    }
    __syncthreads();

    // phase B: 4 row-groups x 64 column-threads, float4 everywhere
    float lossAcc = 0.0f;
    const int c4 = (tid & 63) * 4;
    const int rg = tid >> 6;
#pragma unroll
    for (int k = 0; k < 4; k++) {
        int rr   = rg * 4 + k;
        int code = sBestC[rr];
        int row  = rowBase + rr;
        float4 e  = *(const float4*)(emb + (size_t)code * DIM + c4);
        float4 zv = *(const float4*)(z + (size_t)row * DIM + c4);
        float4 df = make_float4(e.x - zv.x, e.y - zv.y, e.z - zv.z, e.w - zv.w);
        float4 q  = make_float4(zv.x + df.x, zv.y + df.y, zv.z + df.z, zv.w + df.w);
        *(float4*)(out + OFF_ZQ + (size_t)row * DIM + c4) = q;
        lossAcc += df.x * df.x + df.y * df.y + df.z * df.z + df.w * df.w;
        red_add_v4(&g_esum[code * DIM + c4], zv);
    }
#pragma unroll
    for (int o = 16; o >= 1; o >>= 1) lossAcc += __shfl_xor_sync(0xffffffffu, lossAcc, o);
    if (lane == 0) sRed[wid] = lossAcc;
    __syncthreads();
    if (tid < 8) {
        float v = sRed[tid];
#pragma unroll
        for (int o = 4; o >= 1; o >>= 1) v += __shfl_xor_sync(0xffu, v, o, 8);
        if (tid == 0) atomicAdd(&g_loss, v);
    }
}

// ---------------------------------------------------------------------------
__global__ void fin1_kernel(const float* __restrict__ cs, float* __restrict__ out) {
    int k = threadIdx.x;
    float ncs = cs[k] * 0.99f + 0.01f * g_counts[k];
    out[OFF_CS + k] = ncs;
    __shared__ float red[32];
    float v = ncs;
#pragma unroll
    for (int o = 16; o >= 1; o >>= 1) v += __shfl_xor_sync(0xffffffffu, v, o);
    if ((k & 31) == 0) red[k >> 5] = v;
    __syncthreads();
    if (k < 32) {
        float t = red[k];
#pragma unroll
        for (int o = 16; o >= 1; o >>= 1) t += __shfl_xor_sync(0xffffffffu, t, o);
        if (k == 0) {
            g_nsum = t;
            out[OFF_LOSS] = 0.25f * g_loss / (float)(N_TOK * DIM);
        }
    }
}

__global__ void fin2_kernel(const float* __restrict__ avg, float* __restrict__ out) {
    int i = blockIdx.x * blockDim.x + threadIdx.x;
    float navg = avg[i] * 0.99f + 0.01f * g_esum[i];
    out[OFF_AVG + i] = navg;
    int k = i >> 8;
    float ncs = out[OFF_CS + k];
    float csn = (ncs + 1e-6f) / (g_nsum + (float)NCODE * 1e-6f);
    out[OFF_EMB + i] = navg / csn;
}

// ---------------------------------------------------------------------------
extern "C" void kernel_launch(void* const* d_in, const int* in_sizes, int n_in,
                              void* d_out, int out_size) {
    const float* z   = (const float*)d_in[0];
    const float* emb = (const float*)d_in[1];
    const float* cs  = (const float*)d_in[2];
    const float* avg = (const float*)d_in[3];
    float* out = (float*)d_out;

    cudaFuncSetAttribute(vq_main_kernel,
                         cudaFuncAttributeMaxDynamicSharedMemorySize, SM_TOTAL);

    prep_kernel<<<(AC + BC + ZC + EC) / 256, 256>>>(z, emb);
    vq_main_kernel<<<N_TOK / 128, 256, SM_TOTAL>>>();
    outref_kernel<<<N_TOK / 16, 256>>>(z, emb, out);
    fin1_kernel<<<1, 1024>>>(cs, out);
    fin2_kernel<<<(NCODE * DIM) / 256, 256>>>(avg, out);
}

// round 16
// speedup vs baseline: 1.6059x; 1.0997x over previous
#include <cuda_runtime.h>
#include <cuda_bf16.h>
#include <cstdint>

#define N_TOK 32768
#define DIM   256
#define NCODE 1024
#define TAU   3.0f
#define TAU2  0.75f
#define CAP   48

// d_out layout (float32): z_q_st, loss, indices, new_cluster_size,
// new_embedding_avg, new_embedding
#define OFF_ZQ   0
#define OFF_LOSS (N_TOK * DIM)
#define OFF_IDX  (OFF_LOSS + 1)
#define OFF_CS   (OFF_IDX + N_TOK)
#define OFF_AVG  (OFF_CS + NCODE)
#define OFF_EMB  (OFF_AVG + NCODE * DIM)

#define TILE_B   10240                   // 128 rows x 80 B (64 B data + pad)

__device__ __align__(16) float g_enorm[NCODE];
__device__ float g_counts[NCODE];
__device__ __align__(16) float g_esum[NCODE * DIM];
__device__ float g_loss;
__device__ float g_nsum;
// tile-contiguous bf16 images: gAt[block][kc][row*80 + c*2], gBt[n][kc][...]
__device__ __align__(16) uint8_t gAt[(N_TOK / 128) * 8 * TILE_B];   // 21 MB
__device__ __align__(16) uint8_t gBt[(NCODE / 128) * 8 * TILE_B];   // 655 KB
__device__ int g_cnt[N_TOK];
__device__ unsigned g_minu[N_TOK];
__device__ unsigned long long g_cand64[N_TOK * CAP];   // (mapped dist, code)

// ---------------------------------------------------------------------------
__device__ __forceinline__ uint32_t smem_u32(const void* p) {
    uint32_t a;
    asm("{ .reg .u64 t; cvta.to.shared.u64 t, %1; cvt.u32.u64 %0, t; }"
        : "=r"(a) : "l"(p));
    return a;
}
#define MBAR_INIT(a, c) asm volatile("mbarrier.init.shared.b64 [%0], %1;" \
    :: "r"(a), "r"(c) : "memory")
#define MBAR_EXPECT_TX(a, b) asm volatile(                                    \
    "mbarrier.arrive.expect_tx.shared.b64 _, [%0], %1;"                       \
    :: "r"(a), "r"(b) : "memory")
#define MBAR_ARRIVE(a) asm volatile("mbarrier.arrive.shared.b64 _, [%0];"     \
    :: "r"(a) : "memory")
#define MBAR_WAIT(a, ph) do {                                               \
    uint32_t _m = (a), _p = (ph), _d;                                       \
    asm volatile("{\n\t.reg .pred p;\n\t"                                   \
        "mbarrier.try_wait.parity.acquire.cta.shared::cta.b64 p, [%1], %2;\n\t" \
        "selp.b32 %0, 1, 0, p;\n\t}" : "=r"(_d) : "r"(_m), "r"(_p) : "memory"); \
    if (!_d) {                                                              \
        asm volatile("{\n\t.reg .pred P1;\n\tWL%=:\n\t"                     \
            "mbarrier.try_wait.parity.acquire.cta.shared::cta.b64 P1, [%0], %1, 0x989680;\n\t" \
            "@P1 bra.uni WD%=;\n\tbra.uni WL%=;\n\tWD%=:\n\t}"              \
            :: "r"(_m), "r"(_p) : "memory");                                \
    } } while (0)
#define FENCE_ASYNC() asm volatile("fence.proxy.async.shared::cta;" ::: "memory")
#define GROUP_BAR(id) asm volatile("bar.sync %0, 128;" :: "r"(id) : "memory")

__device__ __forceinline__ void bulk_g2s(uint32_t dst, const void* src,
                                         uint32_t bytes, uint32_t mbar) {
    asm volatile(
        "cp.async.bulk.shared::cta.global.mbarrier::complete_tx::bytes "
        "[%0], [%1], %2, [%3];"
        :: "r"(dst), "l"(__cvta_generic_to_global(src)), "r"(bytes), "r"(mbar)
        : "memory");
}
__device__ __forceinline__ void red_add_v4(float* gptr, float4 v) {
    asm volatile("red.global.add.v4.f32 [%0], {%1, %2, %3, %4};"
                 :: "l"(__cvta_generic_to_global(gptr)),
                    "f"(v.x), "f"(v.y), "f"(v.z), "f"(v.w) : "memory");
}

#define LDSM4(r0, r1, r2, r3, addr) asm volatile(                              \
    "ldmatrix.sync.aligned.m8n8.x4.shared.b16 {%0,%1,%2,%3}, [%4];"            \
    : "=r"(r0), "=r"(r1), "=r"(r2), "=r"(r3) : "r"(addr))

#define MMA(c, a0, a1, a2, a3, b0, b1) asm volatile(                           \
    "mma.sync.aligned.m16n8k16.row.col.f32.bf16.bf16.f32 "                     \
    "{%0,%1,%2,%3},{%4,%5,%6,%7},{%8,%9},{%0,%1,%2,%3};"                       \
    : "+f"((c)[0]), "+f"((c)[1]), "+f"((c)[2]), "+f"((c)[3])                   \
    : "r"(a0), "r"(a1), "r"(a2), "r"(a3), "r"(b0), "r"(b1))

__device__ __forceinline__ unsigned mapf(float d) {
    unsigned u = __float_as_uint(d);
    return (u & 0x80000000u) ? ~u : (u | 0x80000000u);
}
__device__ __forceinline__ float unmapf(unsigned x) {
    return (x & 0x80000000u) ? __uint_as_float(x & 0x7fffffffu)
                             : __uint_as_float(~x);
}

// ---------------------------------------------------------------------------
// prep: fp32 -> bf16 tile images + zero scratch + enorm + cs-sum (all fused).
// Range boundaries are multiples of 256 so each 256-thread block is uniform.
#define AC (N_TOK * DIM / 8)             // 1,048,576
#define BC (NCODE * DIM / 8)             // 32,768
#define ZC (NCODE * DIM / 4)             // 65,536
#define EC (NCODE * 32)                  // 32,768 (one warp per code)
#define SC 256                           // one block: sum(cluster_size)
__global__ void prep_kernel(const float* __restrict__ z, const float* __restrict__ emb,
                            const float* __restrict__ cs) {
    __shared__ float sred[8];
    int p = blockIdx.x * blockDim.x + threadIdx.x;
    if (p < AC) {
        int t = p >> 9, w = p & 511;             // tile, chunk-within
        int row = w >> 2, c4 = w & 3;
        int b = t >> 3, kc = t & 7;
        const float* src = z + (size_t)(b * 128 + row) * DIM + kc * 32 + c4 * 8;
        float4 v0 = *(const float4*)src;
        float4 v1 = *(const float4*)(src + 4);
        __nv_bfloat162 o0 = __halves2bfloat162(__float2bfloat16_rn(v0.x), __float2bfloat16_rn(v0.y));
        __nv_bfloat162 o1 = __halves2bfloat162(__float2bfloat16_rn(v0.z), __float2bfloat16_rn(v0.w));
        __nv_bfloat162 o2 = __halves2bfloat162(__float2bfloat16_rn(v1.x), __float2bfloat16_rn(v1.y));
        __nv_bfloat162 o3 = __halves2bfloat162(__float2bfloat16_rn(v1.z), __float2bfloat16_rn(v1.w));
        uint4 pack = {*(uint32_t*)&o0, *(uint32_t*)&o1, *(uint32_t*)&o2, *(uint32_t*)&o3};
        *(uint4*)(gAt + (size_t)t * TILE_B + row * 80 + c4 * 16) = pack;
    } else if (p < AC + BC) {
        int q = p - AC;
        int t = q >> 9, w = q & 511;
        int row = w >> 2, c4 = w & 3;
        const float* src = emb + (size_t)((t >> 3) * 128 + row) * DIM + (t & 7) * 32 + c4 * 8;
        float4 v0 = *(const float4*)src;
        float4 v1 = *(const float4*)(src + 4);
        __nv_bfloat162 o0 = __halves2bfloat162(__float2bfloat16_rn(v0.x), __float2bfloat16_rn(v0.y));
        __nv_bfloat162 o1 = __halves2bfloat162(__float2bfloat16_rn(v0.z), __float2bfloat16_rn(v0.w));
        __nv_bfloat162 o2 = __halves2bfloat162(__float2bfloat16_rn(v1.x), __float2bfloat16_rn(v1.y));
        __nv_bfloat162 o3 = __halves2bfloat162(__float2bfloat16_rn(v1.z), __float2bfloat16_rn(v1.w));
        uint4 pack = {*(uint32_t*)&o0, *(uint32_t*)&o1, *(uint32_t*)&o2, *(uint32_t*)&o3};
        *(uint4*)(gBt + (size_t)t * TILE_B + row * 80 + c4 * 16) = pack;
    } else if (p < AC + BC + ZC) {
        int zi = p - AC - BC;
        ((float4*)g_esum)[zi] = make_float4(0.f, 0.f, 0.f, 0.f);
        if (zi < NCODE / 4) ((float4*)g_counts)[zi] = make_float4(0.f, 0.f, 0.f, 0.f);
        if (zi == 0) g_loss = 0.0f;
    } else if (p < AC + BC + ZC + EC) {
        int q2 = p - AC - BC - ZC;               // enorm: one warp per code
        int w = q2 >> 5, lane = q2 & 31;
        const float4* pe = (const float4*)(emb + (size_t)w * DIM);
        float s = 0.0f;
#pragma unroll
        for (int c = 0; c < 2; c++) {
            float4 v = pe[lane + 32 * c];
            s += v.x * v.x + v.y * v.y + v.z * v.z + v.w * v.w;
        }
#pragma unroll
        for (int o = 16; o >= 1; o >>= 1) s += __shfl_xor_sync(0xffffffffu, s, o);
        if (lane == 0) g_enorm[w] = s;
    } else {
        // cs-sum block (exactly one 256-thread block; branch is block-uniform)
        int t = threadIdx.x;
        float s = cs[t] + cs[t + 256] + cs[t + 512] + cs[t + 768];
#pragma unroll
        for (int o = 16; o >= 1; o >>= 1) s += __shfl_xor_sync(0xffffffffu, s, o);
        if ((t & 31) == 0) sred[t >> 5] = s;
        __syncthreads();
        if (t == 0) {
            float tot = 0.0f;
#pragma unroll
            for (int i = 0; i < 8; i++) tot += sred[i];
            g_nsum = 0.99f * tot + 0.01f * (float)N_TOK;  // sum(counts)==N_TOK
        }
    }
}

// ---------------------------------------------------------------------------
// Main: bulk-copy-fed bf16 HMMA approx GEMM + windowed candidate collection.
// Producer-consumer mbarrier pipeline (full tx-based / empty count=8) —
// warps free-run within the 4-stage window; no per-iter CTA barrier.
// Epilogue syncs only within each 128-thread row-half via named barriers.
// ---------------------------------------------------------------------------
#define STAGE_SZ 20480                   // A 10240 + B 10240
#define SM_EN    81920                   // 4 KB
#define SM_MINU  86016                   // 128 x u32
#define SM_CNT   86528                   // 128 x int
#define SM_MBAR  87040                   // full[4] @ +0..31, empty[4] @ +32..63
#define SM_TOTAL 87104

__global__ __launch_bounds__(256, 2)
void vq_main_kernel() {
    extern __shared__ char smem[];
    const uint32_t sb = smem_u32(smem);
    const int tid  = threadIdx.x;
    const int lane = tid & 31;
    const int wid  = tid >> 5;
    const int wm   = wid >> 2;           // 0..1  (M half)
    const int wn   = wid & 3;            // 0..3  (N quarter, 32 cols)
    const int rowBase = blockIdx.x * 128;

    float*    sEnorm = (float*)(smem + SM_EN);
    unsigned* sMinU  = (unsigned*)(smem + SM_MINU);
    int*      sCnt   = (int*)(smem + SM_CNT);

#pragma unroll
    for (int i = 0; i < 4; i++) sEnorm[tid + i * 256] = g_enorm[tid + i * 256];
    if (tid < 128) { sMinU[tid] = 0xffffffffu; sCnt[tid] = 0; }
    if (tid == 0) {
#pragma unroll
        for (int s = 0; s < 4; s++) {
            MBAR_INIT(sb + SM_MBAR + s * 8, 1);        // full[s]
            MBAR_INIT(sb + SM_MBAR + 32 + s * 8, 8);   // empty[s]
        }
    }
    __syncthreads();
    FENCE_ASYNC();

    // producer: j = n*8 + kc
#define ISSUE(j) do {                                                          \
    int _s = (j) & 3;                                                          \
    uint32_t _st = sb + _s * STAGE_SZ;                                         \
    uint32_t _mb = sb + SM_MBAR + _s * 8;                                      \
    MBAR_EXPECT_TX(_mb, STAGE_SZ);                                             \
    bulk_g2s(_st, gAt + (size_t)(blockIdx.x * 8 + ((j) & 7)) * TILE_B,         \
             TILE_B, _mb);                                                     \
    bulk_g2s(_st + TILE_B, gBt + (size_t)(j) * TILE_B, TILE_B, _mb);           \
} while (0)

    if (tid == 0) { ISSUE(0); ISSUE(1); ISSUE(2); }

    // ldmatrix per-lane address offsets (bytes), row stride 80B
    const uint32_t aOff = (uint32_t)((wm * 64 + (lane & 15)) * 80 + (lane >> 4) * 16);
    const uint32_t bOff = (uint32_t)((wn * 32 + (lane & 7) + ((lane >> 4) << 3)) * 80
                                     + ((lane >> 3) & 1) * 16);

    float acc[4][4][4];
#pragma unroll
    for (int m = 0; m < 4; m++)
#pragma unroll
        for (int nf = 0; nf < 4; nf++)
#pragma unroll
            for (int v = 0; v < 4; v++) acc[m][nf][v] = 0.0f;

    // smem counter, direct global store of packed (dist, code)
#define EMIT(dd, cc, rloc) do {                                                \
    int _p = atomicAdd(&sCnt[rloc], 1);                                        \
    if (_p < CAP)                                                              \
        g_cand64[(size_t)(rowBase + (rloc)) * CAP + _p] =                      \
            ((unsigned long long)mapf(dd) << 32) | (unsigned)(cc);             \
} while (0)

    for (int it = 0; it < 64; it++) {
        // producer step for iter it+3 (backpressure on empty of that stage)
        if (tid == 0) {
            int j = it + 3;
            if (j < 64) {
                if (j >= 4)
                    MBAR_WAIT(sb + SM_MBAR + 32 + (j & 3) * 8, ((j >> 2) - 1) & 1);
                ISSUE(j);
            }
        }

        MBAR_WAIT(sb + SM_MBAR + (it & 3) * 8, (it >> 2) & 1);

        const uint32_t stBase = sb + (it & 3) * STAGE_SZ;
        const uint32_t aB = stBase + aOff;
        const uint32_t bB = stBase + TILE_B + bOff;

#pragma unroll
        for (int s = 0; s < 2; s++) {                    // two k16 steps
            uint32_t b[4][2];
#pragma unroll
            for (int q = 0; q < 2; q++) {
                uint32_t r0, r1, r2, r3;
                LDSM4(r0, r1, r2, r3, bB + q * 1280 + s * 32);
                b[2 * q][0] = r0; b[2 * q][1] = r1;
                b[2 * q + 1][0] = r2; b[2 * q + 1][1] = r3;
            }
#pragma unroll
            for (int m = 0; m < 4; m++) {
                uint32_t a0, a1, a2, a3;
                LDSM4(a0, a1, a2, a3, aB + m * 1280 + s * 32);
#pragma unroll
                for (int nf = 0; nf < 4; nf++)
                    MMA(acc[m][nf], a0, a1, a2, a3, b[nf][0], b[nf][1]);
            }
        }
        // all MMAs issued => all LDSMs of this stage drained; release stage
        if (lane == 0) MBAR_ARRIVE(sb + SM_MBAR + 32 + (it & 3) * 8);

        if ((it & 7) == 7) {                             // end of n-tile
            const int n = it >> 3;
            const int colB = n * 128 + wn * 32 + 2 * (lane & 3);
            // pass 1: settle per-row approx min (group = 4 warps sharing wm)
#pragma unroll
            for (int m = 0; m < 4; m++) {
                int r0 = wm * 64 + m * 16 + (lane >> 2);
                float bd0 = 3.4e38f, bd1 = 3.4e38f;
#pragma unroll
                for (int nf = 0; nf < 4; nf++) {
                    float2 en = *(const float2*)&sEnorm[colB + nf * 8];
                    bd0 = fminf(bd0, fminf(en.x - 2.0f * acc[m][nf][0],
                                           en.y - 2.0f * acc[m][nf][1]));
                    bd1 = fminf(bd1, fminf(en.x - 2.0f * acc[m][nf][2],
                                           en.y - 2.0f * acc[m][nf][3]));
                }
#pragma unroll
                for (int off = 1; off <= 2; off <<= 1) {
                    bd0 = fminf(bd0, __shfl_xor_sync(0xffffffffu, bd0, off));
                    bd1 = fminf(bd1, __shfl_xor_sync(0xffffffffu, bd1, off));
                }
                if ((lane & 3) == 0) {
                    atomicMin(&sMinU[r0], mapf(bd0));
                    atomicMin(&sMinU[r0 + 8], mapf(bd1));
                }
            }
            GROUP_BAR(1 + wm);
            // pass 2: emit candidates within TAU of settled min.
            // (A faster warp may already be atomicMin-ing future-tile values
            //  into sMinU; that only shrinks thr toward final_min+TAU, which
            //  still exceeds final_min+2E, so the true argmin is always kept.)
#pragma unroll
            for (int m = 0; m < 4; m++) {
                int r0 = wm * 64 + m * 16 + (lane >> 2);
                float thr0 = unmapf(sMinU[r0]) + TAU;
                float thr1 = unmapf(sMinU[r0 + 8]) + TAU;
#pragma unroll
                for (int nf = 0; nf < 4; nf++) {
                    float2 en = *(const float2*)&sEnorm[colB + nf * 8];
                    float d0 = en.x - 2.0f * acc[m][nf][0];
                    float d1 = en.y - 2.0f * acc[m][nf][1];
                    float d2 = en.x - 2.0f * acc[m][nf][2];
                    float d3 = en.y - 2.0f * acc[m][nf][3];
                    int c0 = colB + nf * 8;
                    if (d0 < thr0) EMIT(d0, c0,     r0);
                    if (d1 < thr0) EMIT(d1, c0 + 1, r0);
                    if (d2 < thr1) EMIT(d2, c0,     r0 + 8);
                    if (d3 < thr1) EMIT(d3, c0 + 1, r0 + 8);
                    acc[m][nf][0] = 0.0f; acc[m][nf][1] = 0.0f;
                    acc[m][nf][2] = 0.0f; acc[m][nf][3] = 0.0f;
                }
            }
        }
    }
    __syncthreads();                                     // all emits done

    // dump counts (clamped) + final per-row approx min
    if (tid < 128) {
        int c = sCnt[tid];
        g_cnt[rowBase + tid]  = c > CAP ? CAP : c;
        g_minu[rowBase + tid] = sMinU[tid];
    }
}

// ---------------------------------------------------------------------------
// Refine + output kernel (R15): dual-row ILP, single-survivor shortcut.
// ---------------------------------------------------------------------------
__global__ __launch_bounds__(256, 8)
void outref_kernel(const float* __restrict__ z, const float* __restrict__ emb,
                   float* __restrict__ out) {
    __shared__ int   sBestC[16];
    __shared__ float sRed[8];
    const int tid  = threadIdx.x;
    const int lane = tid & 31;
    const int wid  = tid >> 5;
    const int rowBase = blockIdx.x * 16;

    {
        const int r0 = rowBase + wid * 2;
        const int r1 = r0 + 1;
        int cnt0 = g_cnt[r0], cnt1 = g_cnt[r1];
        unsigned mthr0 = mapf(unmapf(g_minu[r0]) + TAU2);
        unsigned mthr1 = mapf(unmapf(g_minu[r1]) + TAU2);
        const float* zr0 = z + (size_t)r0 * DIM;
        const float* zr1 = z + (size_t)r1 * DIM;
        float zv0[8], zv1[8];
#pragma unroll
        for (int j = 0; j < 8; j++) { zv0[j] = zr0[lane + 32 * j]; zv1[j] = zr1[lane + 32 * j]; }

        unsigned long long pk0 = ~0ull, pk1 = ~0ull;
        if (lane < cnt0) pk0 = g_cand64[(size_t)r0 * CAP + lane];
        if (lane < cnt1) pk1 = g_cand64[(size_t)r1 * CAP + lane];
        unsigned msk0 = __ballot_sync(0xffffffffu,
                            lane < cnt0 && (unsigned)(pk0 >> 32) <= mthr0);
        unsigned msk1 = __ballot_sync(0xffffffffu,
                            lane < cnt1 && (unsigned)(pk1 >> 32) <= mthr1);

        float bestd0 = 3.4e38f, bestd1 = 3.4e38f;
        int   bestc0 = 0x7fffffff, bestc1 = 0x7fffffff;

        if (cnt0 <= 32 && __popc(msk0) == 1) {
            int src = __ffs(msk0) - 1;
            bestc0 = (int)(unsigned)(__shfl_sync(0xffffffffu, pk0, src) & 0xffffffffull);
            bestd0 = -3.4e38f;
            msk0 = 0;
        }
        if (cnt1 <= 32 && __popc(msk1) == 1) {
            int src = __ffs(msk1) - 1;
            bestc1 = (int)(unsigned)(__shfl_sync(0xffffffffu, pk1, src) & 0xffffffffull);
            bestd1 = -3.4e38f;
            msk1 = 0;
        }

        while (msk0 | msk1) {
            int c0 = 0, c1 = 0; bool a0 = false, a1 = false;
            if (msk0) {
                int src = __ffs(msk0) - 1; msk0 &= msk0 - 1;
                c0 = (int)(unsigned)(__shfl_sync(0xffffffffu, pk0, src) & 0xffffffffull);
                a0 = true;
            }
            if (msk1) {
                int src = __ffs(msk1) - 1; msk1 &= msk1 - 1;
                c1 = (int)(unsigned)(__shfl_sync(0xffffffffu, pk1, src) & 0xffffffffull);
                a1 = true;
            }
            const float* e0 = emb + (size_t)c0 * DIM;
            const float* e1 = emb + (size_t)c1 * DIM;
            float dot0 = 0.0f, dot1 = 0.0f;
#pragma unroll
            for (int j = 0; j < 8; j++) {
                dot0 += zv0[j] * e0[lane + 32 * j];
                dot1 += zv1[j] * e1[lane + 32 * j];
            }
#pragma unroll
            for (int o = 16; o >= 1; o >>= 1) {
                dot0 += __shfl_xor_sync(0xffffffffu, dot0, o);
                dot1 += __shfl_xor_sync(0xffffffffu, dot1, o);
            }
            if (a0) {
                float dd = g_enorm[c0] - 2.0f * dot0;
                if (dd < bestd0 || (dd == bestd0 && c0 < bestc0)) { bestd0 = dd; bestc0 = c0; }
            }
            if (a1) {
                float dd = g_enorm[c1] - 2.0f * dot1;
                if (dd < bestd1 || (dd == bestd1 && c1 < bestc1)) { bestd1 = dd; bestc1 = c1; }
            }
        }

        for (int base = 32; base < cnt0; base += 32) {
            int ci = base + lane;
            unsigned long long pk = ~0ull;
            if (ci < cnt0) pk = g_cand64[(size_t)r0 * CAP + ci];
            bool pass = (ci < cnt0) && ((unsigned)(pk >> 32) <= mthr0);
            unsigned msk = __ballot_sync(0xffffffffu, pass);
            while (msk) {
                int src = __ffs(msk) - 1; msk &= msk - 1;
                int c = (int)(unsigned)(__shfl_sync(0xffffffffu, pk, src) & 0xffffffffull);
                const float* er = emb + (size_t)c * DIM;
                float dot = 0.0f;
#pragma unroll
                for (int j = 0; j < 8; j++) dot += zv0[j] * er[lane + 32 * j];
#pragma unroll
                for (int o = 16; o >= 1; o >>= 1) dot += __shfl_xor_sync(0xffffffffu, dot, o);
                float dd = g_enorm[c] - 2.0f * dot;
                if (dd < bestd0 || (dd == bestd0 && c < bestc0)) { bestd0 = dd; bestc0 = c; }
            }
        }
        for (int base = 32; base < cnt1; base += 32) {
            int ci = base + lane;
            unsigned long long pk = ~0ull;
            if (ci < cnt1) pk = g_cand64[(size_t)r1 * CAP + ci];
            bool pass = (ci < cnt1) && ((unsigned)(pk >> 32) <= mthr1);
            unsigned msk = __ballot_sync(0xffffffffu, pass);
            while (msk) {
                int src = __ffs(msk) - 1; msk &= msk - 1;
                int c = (int)(unsigned)(__shfl_sync(0xffffffffu, pk, src) & 0xffffffffull);
                const float* er = emb + (size_t)c * DIM;
                float dot = 0.0f;
#pragma unroll
                for (int j = 0; j < 8; j++) dot += zv1[j] * er[lane + 32 * j];
#pragma unroll
                for (int o = 16; o >= 1; o >>= 1) dot += __shfl_xor_sync(0xffffffffu, dot, o);
                float dd = g_enorm[c] - 2.0f * dot;
                if (dd < bestd1 || (dd == bestd1 && c < bestc1)) { bestd1 = dd; bestc1 = c; }
            }
        }

        if (lane == 0) {
            sBestC[wid * 2]     = bestc0;
            sBestC[wid * 2 + 1] = bestc1;
            out[OFF_IDX + r0] = (float)bestc0;
            out[OFF_IDX + r1] = (float)bestc1;
            atomicAdd(&g_counts[bestc0], 1.0f);
            atomicAdd(&g_counts[bestc1], 1.0f);
        }
    }
    __syncthreads();

    // phase B: 4 row-groups x 64 column-threads, float4 everywhere
    float lossAcc = 0.0f;
    const int c4 = (tid & 63) * 4;
    const int rg = tid >> 6;
#pragma unroll
    for (int k = 0; k < 4; k++) {
        int rr   = rg * 4 + k;
        int code = sBestC[rr];
        int row  = rowBase + rr;
        float4 e  = *(const float4*)(emb + (size_t)code * DIM + c4);
        float4 zv = *(const float4*)(z + (size_t)row * DIM + c4);
        float4 df = make_float4(e.x - zv.x, e.y - zv.y, e.z - zv.z, e.w - zv.w);
        float4 q  = make_float4(zv.x + df.x, zv.y + df.y, zv.z + df.z, zv.w + df.w);
        *(float4*)(out + OFF_ZQ + (size_t)row * DIM + c4) = q;
        lossAcc += df.x * df.x + df.y * df.y + df.z * df.z + df.w * df.w;
        red_add_v4(&g_esum[code * DIM + c4], zv);
    }
#pragma unroll
    for (int o = 16; o >= 1; o >>= 1) lossAcc += __shfl_xor_sync(0xffffffffu, lossAcc, o);
    if (lane == 0) sRed[wid] = lossAcc;
    __syncthreads();
    if (tid < 8) {
        float v = sRed[tid];
#pragma unroll
        for (int o = 4; o >= 1; o >>= 1) v += __shfl_xor_sync(0xffu, v, o, 8);
        if (tid == 0) atomicAdd(&g_loss, v);
    }
}

// ---------------------------------------------------------------------------
// fin2: new_cluster_size, loss, new_embedding_avg, new_embedding (fin1 folded:
// g_nsum precomputed in prep since sum(counts) == N_TOK exactly).
// ---------------------------------------------------------------------------
__global__ void fin2_kernel(const float* __restrict__ cs,
                            const float* __restrict__ avg,
                            float* __restrict__ out) {
    int i = blockIdx.x * blockDim.x + threadIdx.x;
    int k = i >> 8;
    float ncs = cs[k] * 0.99f + 0.01f * g_counts[k];
    float navg = avg[i] * 0.99f + 0.01f * g_esum[i];
    out[OFF_AVG + i] = navg;
    float csn = (ncs + 1e-6f) / (g_nsum + (float)NCODE * 1e-6f);
    out[OFF_EMB + i] = navg / csn;
    if ((i & 255) == 0) out[OFF_CS + k] = ncs;
    if (i == 0) out[OFF_LOSS] = 0.25f * g_loss / (float)(N_TOK * DIM);
}

// ---------------------------------------------------------------------------
extern "C" void kernel_launch(void* const* d_in, const int* in_sizes, int n_in,
                              void* d_out, int out_size) {
    const float* z   = (const float*)d_in[0];
    const float* emb = (const float*)d_in[1];
    const float* cs  = (const float*)d_in[2];
    const float* avg = (const float*)d_in[3];
    float* out = (float*)d_out;

    cudaFuncSetAttribute(vq_main_kernel,
                         cudaFuncAttributeMaxDynamicSharedMemorySize, SM_TOTAL);

    prep_kernel<<<(AC + BC + ZC + EC + SC) / 256, 256>>>(z, emb, cs);
    vq_main_kernel<<<N_TOK / 128, 256, SM_TOTAL>>>();
    outref_kernel<<<N_TOK / 16, 256>>>(z, emb, out);
    fin2_kernel<<<(NCODE * DIM) / 256, 256>>>(cs, avg, out);
}